// round 1
// baseline (speedup 1.0000x reference)
#include <cuda_runtime.h>
#include <math.h>

// Problem constants (fixed shapes from reference)
#define BB 8
#define SS 2048
#define QQ 2048
#define DD 1024

// Scratch: f_att/tanh buffer and sim/softmax buffer (B*S*Q floats each, 134MB each)
__device__ float g_t1[(size_t)BB * SS * QQ];
__device__ float g_t2[(size_t)BB * SS * QQ];

// ---------------------------------------------------------------------------
// Kernel 1: g_t1[b,s,q] = tanh( sum_d source[b,s,d]*wk[d,q] + wq[s,d]*query[b,q,d] )
// Tiled 64x64 output, BK=16, 256 threads, 4x4 register tile per thread.
// ---------------------------------------------------------------------------
__global__ void k_fatt(const float* __restrict__ src,
                       const float* __restrict__ qry,
                       const float* __restrict__ wk,
                       const float* __restrict__ wq)
{
    const int b  = blockIdx.z;
    const int s0 = blockIdx.y * 64;
    const int q0 = blockIdx.x * 64;

    __shared__ float As[64][17];  // source tile [s][k]
    __shared__ float Cs[64][17];  // wq tile     [s][k]
    __shared__ float Bs[16][65];  // wk tile     [k][q]
    __shared__ float Ds[16][65];  // query tile  [k][q] (transposed load)

    const float* srcB = src + (size_t)b * SS * DD;
    const float* qryB = qry + (size_t)b * QQ * DD;

    const int tid = threadIdx.x;
    const int ty  = tid >> 4;   // 0..15
    const int tx  = tid & 15;   // 0..15

    float acc[4][4];
#pragma unroll
    for (int i = 0; i < 4; i++)
#pragma unroll
        for (int j = 0; j < 4; j++) acc[i][j] = 0.f;

    for (int k0 = 0; k0 < DD; k0 += 16) {
        // load As/Cs: 64x16
#pragma unroll
        for (int idx = tid; idx < 64 * 16; idx += 256) {
            int r = idx >> 4, c = idx & 15;
            As[r][c] = srcB[(size_t)(s0 + r) * DD + k0 + c];
            Cs[r][c] = wq[(size_t)(s0 + r) * DD + k0 + c];
        }
        // load Bs: 16x64 from wk [d][q]
#pragma unroll
        for (int idx = tid; idx < 16 * 64; idx += 256) {
            int r = idx >> 6, c = idx & 63;
            Bs[r][c] = wk[(size_t)(k0 + r) * QQ + q0 + c];
        }
        // load Ds transposed: Ds[kk][qq] = query[b, q0+qq, k0+kk]
#pragma unroll
        for (int idx = tid; idx < 64 * 16; idx += 256) {
            int qq = idx >> 4, kk = idx & 15;
            Ds[kk][qq] = qryB[(size_t)(q0 + qq) * DD + k0 + kk];
        }
        __syncthreads();

#pragma unroll
        for (int kk = 0; kk < 16; kk++) {
            float a[4], c[4], bb[4], dd[4];
#pragma unroll
            for (int i = 0; i < 4; i++) { a[i] = As[ty * 4 + i][kk]; c[i] = Cs[ty * 4 + i][kk]; }
#pragma unroll
            for (int j = 0; j < 4; j++) { bb[j] = Bs[kk][tx * 4 + j]; dd[j] = Ds[kk][tx * 4 + j]; }
#pragma unroll
            for (int i = 0; i < 4; i++)
#pragma unroll
                for (int j = 0; j < 4; j++)
                    acc[i][j] += a[i] * bb[j] + c[i] * dd[j];
        }
        __syncthreads();
    }

    float* outB = g_t1 + (size_t)b * SS * QQ;
#pragma unroll
    for (int i = 0; i < 4; i++)
#pragma unroll
        for (int j = 0; j < 4; j++)
            outB[(size_t)(s0 + ty * 4 + i) * QQ + (q0 + tx * 4 + j)] = tanhf(acc[i][j]);
}

// ---------------------------------------------------------------------------
// Kernel 2: g_t2[b,s,t] = sum_q g_t1[b,s,q] * kernel[q,t]   (K = QQ = 2048)
// ---------------------------------------------------------------------------
__global__ void k_sim(const float* __restrict__ kern)
{
    const int b  = blockIdx.z;
    const int s0 = blockIdx.y * 64;
    const int t0 = blockIdx.x * 64;

    __shared__ float As[64][17];  // g_t1 tile [s][k]
    __shared__ float Bs[16][65];  // kernel tile [k][t]

    const float* A = g_t1 + (size_t)b * SS * QQ;

    const int tid = threadIdx.x;
    const int ty  = tid >> 4;
    const int tx  = tid & 15;

    float acc[4][4];
#pragma unroll
    for (int i = 0; i < 4; i++)
#pragma unroll
        for (int j = 0; j < 4; j++) acc[i][j] = 0.f;

    for (int k0 = 0; k0 < QQ; k0 += 16) {
#pragma unroll
        for (int idx = tid; idx < 64 * 16; idx += 256) {
            int r = idx >> 4, c = idx & 15;
            As[r][c] = A[(size_t)(s0 + r) * QQ + k0 + c];
        }
#pragma unroll
        for (int idx = tid; idx < 16 * 64; idx += 256) {
            int r = idx >> 6, c = idx & 63;
            Bs[r][c] = kern[(size_t)(k0 + r) * QQ + t0 + c];
        }
        __syncthreads();

#pragma unroll
        for (int kk = 0; kk < 16; kk++) {
            float a[4], bb[4];
#pragma unroll
            for (int i = 0; i < 4; i++) a[i] = As[ty * 4 + i][kk];
#pragma unroll
            for (int j = 0; j < 4; j++) bb[j] = Bs[kk][tx * 4 + j];
#pragma unroll
            for (int i = 0; i < 4; i++)
#pragma unroll
                for (int j = 0; j < 4; j++)
                    acc[i][j] += a[i] * bb[j];
        }
        __syncthreads();
    }

    float* outB = g_t2 + (size_t)b * SS * QQ;
#pragma unroll
    for (int i = 0; i < 4; i++)
#pragma unroll
        for (int j = 0; j < 4; j++)
            outB[(size_t)(s0 + ty * 4 + i) * QQ + (t0 + tx * 4 + j)] = acc[i][j];
}

// ---------------------------------------------------------------------------
// Kernel 3: in-place row softmax on g_t2 (B*S rows, each QQ long)
// ---------------------------------------------------------------------------
__global__ void k_softmax()
{
    float* p = g_t2 + (size_t)blockIdx.x * QQ;
    const int tid = threadIdx.x;  // 256

    __shared__ float red[32];

    // 1) max
    float m = -INFINITY;
    for (int i = tid; i < QQ; i += 256) m = fmaxf(m, p[i]);
#pragma unroll
    for (int o = 16; o > 0; o >>= 1) m = fmaxf(m, __shfl_xor_sync(0xffffffffu, m, o));
    if ((tid & 31) == 0) red[tid >> 5] = m;
    __syncthreads();
    if (tid < 32) {
        float v = (tid < 8) ? red[tid] : -INFINITY;
#pragma unroll
        for (int o = 4; o > 0; o >>= 1) v = fmaxf(v, __shfl_xor_sync(0xffffffffu, v, o));
        red[tid] = v;
    }
    __syncthreads();
    m = red[0];
    __syncthreads();

    // 2) exp + sum
    float sum = 0.f;
    for (int i = tid; i < QQ; i += 256) {
        float e = __expf(p[i] - m);
        p[i] = e;
        sum += e;
    }
#pragma unroll
    for (int o = 16; o > 0; o >>= 1) sum += __shfl_xor_sync(0xffffffffu, sum, o);
    if ((tid & 31) == 0) red[tid >> 5] = sum;
    __syncthreads();
    if (tid < 32) {
        float v = (tid < 8) ? red[tid] : 0.f;
#pragma unroll
        for (int o = 4; o > 0; o >>= 1) v += __shfl_xor_sync(0xffffffffu, v, o);
        red[tid] = v;
    }
    __syncthreads();
    const float inv = 1.0f / red[0];

    // 3) normalize
    for (int i = tid; i < QQ; i += 256) p[i] *= inv;
}

// ---------------------------------------------------------------------------
// Kernel 4: out[b,q,d] = sum_s g_t2[b,s,q] * source[b,s,d]   (A^T @ B, K = SS)
// ---------------------------------------------------------------------------
__global__ void k_out(const float* __restrict__ src, float* __restrict__ out)
{
    const int b  = blockIdx.z;
    const int q0 = blockIdx.y * 64;
    const int d0 = blockIdx.x * 64;

    __shared__ float As[16][65];  // sm tile  [k(s)][q]
    __shared__ float Bs[16][65];  // src tile [k(s)][d]

    const float* A    = g_t2 + (size_t)b * SS * QQ;
    const float* srcB = src + (size_t)b * SS * DD;

    const int tid = threadIdx.x;
    const int ty  = tid >> 4;
    const int tx  = tid & 15;

    float acc[4][4];
#pragma unroll
    for (int i = 0; i < 4; i++)
#pragma unroll
        for (int j = 0; j < 4; j++) acc[i][j] = 0.f;

    for (int k0 = 0; k0 < SS; k0 += 16) {
#pragma unroll
        for (int idx = tid; idx < 16 * 64; idx += 256) {
            int r = idx >> 6, c = idx & 63;
            As[r][c] = A[(size_t)(k0 + r) * QQ + q0 + c];
            Bs[r][c] = srcB[(size_t)(k0 + r) * DD + d0 + c];
        }
        __syncthreads();

#pragma unroll
        for (int kk = 0; kk < 16; kk++) {
            float a[4], bb[4];
#pragma unroll
            for (int i = 0; i < 4; i++) a[i] = As[kk][ty * 4 + i];
#pragma unroll
            for (int j = 0; j < 4; j++) bb[j] = Bs[kk][tx * 4 + j];
#pragma unroll
            for (int i = 0; i < 4; i++)
#pragma unroll
                for (int j = 0; j < 4; j++)
                    acc[i][j] += a[i] * bb[j];
        }
        __syncthreads();
    }

#pragma unroll
    for (int i = 0; i < 4; i++)
#pragma unroll
        for (int j = 0; j < 4; j++)
            out[((size_t)b * QQ + (q0 + ty * 4 + i)) * DD + (d0 + tx * 4 + j)] = acc[i][j];
}

// ---------------------------------------------------------------------------
// Launcher
// ---------------------------------------------------------------------------
extern "C" void kernel_launch(void* const* d_in, const int* in_sizes, int n_in,
                              void* d_out, int out_size)
{
    const float* src  = (const float*)d_in[0];  // (B,S,D)
    const float* qry  = (const float*)d_in[1];  // (B,Q,D)
    const float* kern = (const float*)d_in[2];  // (S,Q)  == (Q,T)
    const float* wk   = (const float*)d_in[3];  // (D,Q)
    const float* wq   = (const float*)d_in[4];  // (S,D)
    float* out = (float*)d_out;                 // (B,Q,D)

    dim3 blk(256);

    // 1) f_att + tanh
    k_fatt<<<dim3(QQ / 64, SS / 64, BB), blk>>>(src, qry, wk, wq);
    // 2) sim = tanh(f_att) @ kernel
    k_sim<<<dim3(QQ / 64, SS / 64, BB), blk>>>(kern);
    // 3) softmax over last axis
    k_softmax<<<BB * SS, blk>>>();
    // 4) out = sm^T @ source
    k_out<<<dim3(DD / 64, QQ / 64, BB), blk>>>(src, out);
}

// round 4
// speedup vs baseline: 5.9284x; 5.9284x over previous
#include <cuda_runtime.h>
#include <cstdint>
#include <math.h>

// Shapes (fixed)
#define BB 8
#define SS 2048
#define QQ 2048
#define DD 1024

// ---------------------------------------------------------------------------
// Scratch (device globals; no allocations allowed)
// ---------------------------------------------------------------------------
__device__ float g_t1[(size_t)BB * SS * QQ];          // 134 MB
__device__ float g_t2[(size_t)BB * SS * QQ];          // 134 MB
__device__ float g_wkT[(size_t)QQ * DD];              // 8 MB   wkT[q][d]
__device__ float g_kernT[(size_t)QQ * QQ];            // 16 MB  kernT[t][q]
__device__ float g_srcT[(size_t)BB * DD * SS];        // 64 MB  srcT[b][d][s]

// ---------------------------------------------------------------------------
// mma.sync tf32 helpers (baseline PTX, no sm_103a-only features)
// ---------------------------------------------------------------------------
__device__ __forceinline__ uint32_t f32_to_tf32(float x) {
    uint32_t r;
    asm("cvt.rna.tf32.f32 %0, %1;" : "=r"(r) : "f"(x));
    return r;
}

__device__ __forceinline__ void mma_tf32(float* d, const uint32_t* a, const uint32_t* b) {
    asm volatile(
        "mma.sync.aligned.m16n8k8.row.col.f32.tf32.tf32.f32 "
        "{%0,%1,%2,%3}, {%4,%5,%6,%7}, {%8,%9}, {%0,%1,%2,%3};\n"
        : "+f"(d[0]), "+f"(d[1]), "+f"(d[2]), "+f"(d[3])
        : "r"(a[0]), "r"(a[1]), "r"(a[2]), "r"(a[3]), "r"(b[0]), "r"(b[1]));
}

__device__ __forceinline__ void cp_async16(uint32_t smem_addr, const void* gptr) {
    asm volatile("cp.async.cg.shared.global [%0], [%1], 16;"
                 :: "r"(smem_addr), "l"(gptr));
}
#define CP_COMMIT() asm volatile("cp.async.commit_group;" ::: "memory")
#define CP_WAIT1()  asm volatile("cp.async.wait_group 1;" ::: "memory")

// ---------------------------------------------------------------------------
// tf32 GEMM: C[b][m][n] (+= Cadd) (tanh) with C = sum_k A[b][m][k]*B[b][n][k]
// 128x128 CTA tile, BK=16, 256 threads (8 warps: 4(M) x 2(N)), warp tile 32x64.
// Double-buffered cp.async.
// ---------------------------------------------------------------------------
#define BM 128
#define BN 128
#define BK 16
#define PAD 4
#define LDT (BK + PAD)   // 20 floats per row

__global__ void __launch_bounds__(256, 2)
gemm_mma(const float* __restrict__ A, const float* __restrict__ B, float* __restrict__ C,
         const float* __restrict__ Cadd,
         int lda, int ldb, int ldc, int K,
         long long strideA, long long strideB, long long strideC, long long strideAdd,
         int do_tanh)
{
    __shared__ float As[2][BM][LDT];
    __shared__ float Bs[2][BN][LDT];

    const int tid = threadIdx.x;
    const int wid = tid >> 5;
    const int lane = tid & 31;
    const int warp_row = wid >> 1;   // 0..3 -> M
    const int warp_col = wid & 1;    // 0..1 -> N

    const int b  = blockIdx.z;
    const int m0 = blockIdx.y * BM;
    const int n0 = blockIdx.x * BN;

    const float* Ab = A + (size_t)b * strideA + (size_t)m0 * lda;
    const float* Bb = B + (size_t)b * strideB + (size_t)n0 * ldb;

    // tile-load indices (2 float4 per thread per tile)
    const int l_row0 = tid >> 2;            // 0..63  (+64 for second chunk)
    const int l_c4   = (tid & 3) * 4;       // 0,4,8,12

    float acc[2][8][4];
#pragma unroll
    for (int i = 0; i < 2; i++)
#pragma unroll
        for (int j = 0; j < 8; j++)
#pragma unroll
            for (int r = 0; r < 4; r++) acc[i][j][r] = 0.f;

    const int ntiles = K / BK;

    // prologue: stage 0
    {
        const float* ap = Ab + (size_t)l_row0 * lda + l_c4;
        const float* bp = Bb + (size_t)l_row0 * ldb + l_c4;
        cp_async16((uint32_t)__cvta_generic_to_shared(&As[0][l_row0][l_c4]), ap);
        cp_async16((uint32_t)__cvta_generic_to_shared(&As[0][l_row0 + 64][l_c4]),
                   ap + (size_t)64 * lda);
        cp_async16((uint32_t)__cvta_generic_to_shared(&Bs[0][l_row0][l_c4]), bp);
        cp_async16((uint32_t)__cvta_generic_to_shared(&Bs[0][l_row0 + 64][l_c4]),
                   bp + (size_t)64 * ldb);
        CP_COMMIT();
    }

    const int a_row = warp_row * 32 + (lane >> 2);
    const int b_row = warp_col * 64 + (lane >> 2);
    const int kq    = lane & 3;

    for (int t = 0; t < ntiles; t++) {
        const int cur = t & 1;
        const int nxt = cur ^ 1;

        if (t + 1 < ntiles) {
            const int k0 = (t + 1) * BK;
            const float* ap = Ab + (size_t)l_row0 * lda + k0 + l_c4;
            const float* bp = Bb + (size_t)l_row0 * ldb + k0 + l_c4;
            cp_async16((uint32_t)__cvta_generic_to_shared(&As[nxt][l_row0][l_c4]), ap);
            cp_async16((uint32_t)__cvta_generic_to_shared(&As[nxt][l_row0 + 64][l_c4]),
                       ap + (size_t)64 * lda);
            cp_async16((uint32_t)__cvta_generic_to_shared(&Bs[nxt][l_row0][l_c4]), bp);
            cp_async16((uint32_t)__cvta_generic_to_shared(&Bs[nxt][l_row0 + 64][l_c4]),
                       bp + (size_t)64 * ldb);
        }
        CP_COMMIT();
        CP_WAIT1();            // stage `cur` complete
        __syncthreads();

#pragma unroll
        for (int ks = 0; ks < 2; ks++) {   // two k-steps of 8
            const int kb = ks * 8 + kq;
            uint32_t afr[2][4];
#pragma unroll
            for (int i = 0; i < 2; i++) {
                const int r = a_row + i * 16;
                afr[i][0] = f32_to_tf32(As[cur][r][kb]);
                afr[i][1] = f32_to_tf32(As[cur][r + 8][kb]);
                afr[i][2] = f32_to_tf32(As[cur][r][kb + 4]);
                afr[i][3] = f32_to_tf32(As[cur][r + 8][kb + 4]);
            }
            uint32_t bfr[8][2];
#pragma unroll
            for (int j = 0; j < 8; j++) {
                const int r = b_row + j * 8;
                bfr[j][0] = f32_to_tf32(Bs[cur][r][kb]);
                bfr[j][1] = f32_to_tf32(Bs[cur][r][kb + 4]);
            }
#pragma unroll
            for (int i = 0; i < 2; i++)
#pragma unroll
                for (int j = 0; j < 8; j++)
                    mma_tf32(acc[i][j], afr[i], bfr[j]);
        }
        __syncthreads();
    }

    // Epilogue
    float* Cb = C + (size_t)b * strideC;
    const float* Addb = Cadd ? (Cadd + (size_t)b * strideAdd) : nullptr;

#pragma unroll
    for (int i = 0; i < 2; i++) {
        const int row0 = m0 + warp_row * 32 + i * 16 + (lane >> 2);
#pragma unroll
        for (int j = 0; j < 8; j++) {
            const int col = n0 + warp_col * 64 + j * 8 + 2 * (lane & 3);
#pragma unroll
            for (int r = 0; r < 2; r++) {
                const size_t off = (size_t)(row0 + r * 8) * ldc + col;
                float2 v;
                v.x = acc[i][j][r * 2 + 0];
                v.y = acc[i][j][r * 2 + 1];
                if (Addb) {
                    float2 a = *reinterpret_cast<const float2*>(Addb + off);
                    v.x += a.x; v.y += a.y;
                }
                if (do_tanh) { v.x = tanhf(v.x); v.y = tanhf(v.y); }
                *reinterpret_cast<float2*>(Cb + off) = v;
            }
        }
    }
}

// ---------------------------------------------------------------------------
// Batched tiled transpose: out[b][c][r] = in[b][r][c]   (R x C -> C x R)
// ---------------------------------------------------------------------------
__global__ void k_transpose(const float* __restrict__ in, float* __restrict__ out,
                            int R, int C, long long sIn, long long sOut)
{
    __shared__ float tile[32][33];
    const float* inb = in + (size_t)blockIdx.z * sIn;
    float* outb = out + (size_t)blockIdx.z * sOut;
    const int c0 = blockIdx.x * 32;
    const int r0 = blockIdx.y * 32;

#pragma unroll
    for (int i = threadIdx.y; i < 32; i += 8)
        tile[i][threadIdx.x] = inb[(size_t)(r0 + i) * C + c0 + threadIdx.x];
    __syncthreads();
#pragma unroll
    for (int i = threadIdx.y; i < 32; i += 8)
        outb[(size_t)(c0 + i) * R + r0 + threadIdx.x] = tile[threadIdx.x][i];
}

// ---------------------------------------------------------------------------
// In-place row softmax on g_t2 (B*S rows of length QQ)
// ---------------------------------------------------------------------------
__global__ void k_softmax()
{
    float* p = g_t2 + (size_t)blockIdx.x * QQ;
    const int tid = threadIdx.x;  // 256

    __shared__ float red[32];

    float m = -INFINITY;
    for (int i = tid; i < QQ; i += 256) m = fmaxf(m, p[i]);
#pragma unroll
    for (int o = 16; o > 0; o >>= 1) m = fmaxf(m, __shfl_xor_sync(0xffffffffu, m, o));
    if ((tid & 31) == 0) red[tid >> 5] = m;
    __syncthreads();
    if (tid < 32) {
        float v = (tid < 8) ? red[tid] : -INFINITY;
#pragma unroll
        for (int o = 4; o > 0; o >>= 1) v = fmaxf(v, __shfl_xor_sync(0xffffffffu, v, o));
        red[tid] = v;
    }
    __syncthreads();
    m = red[0];
    __syncthreads();

    float sum = 0.f;
    for (int i = tid; i < QQ; i += 256) {
        float e = __expf(p[i] - m);
        p[i] = e;
        sum += e;
    }
#pragma unroll
    for (int o = 16; o > 0; o >>= 1) sum += __shfl_xor_sync(0xffffffffu, sum, o);
    if ((tid & 31) == 0) red[tid >> 5] = sum;
    __syncthreads();
    if (tid < 32) {
        float v = (tid < 8) ? red[tid] : 0.f;
#pragma unroll
        for (int o = 4; o > 0; o >>= 1) v += __shfl_xor_sync(0xffffffffu, v, o);
        red[tid] = v;
    }
    __syncthreads();
    const float inv = 1.0f / red[0];

    for (int i = tid; i < QQ; i += 256) p[i] *= inv;
}

// ---------------------------------------------------------------------------
// Launcher
// ---------------------------------------------------------------------------
extern "C" void kernel_launch(void* const* d_in, const int* in_sizes, int n_in,
                              void* d_out, int out_size)
{
    const float* src  = (const float*)d_in[0];  // (B,S,D)
    const float* qry  = (const float*)d_in[1];  // (B,Q,D)
    const float* kern = (const float*)d_in[2];  // (Q,T)
    const float* wk   = (const float*)d_in[3];  // (D,Q)
    const float* wq   = (const float*)d_in[4];  // (S,D)
    float* out = (float*)d_out;                 // (B,Q,D)

    float *t1, *t2, *wkT, *kernT, *srcT;
    cudaGetSymbolAddress((void**)&t1, g_t1);
    cudaGetSymbolAddress((void**)&t2, g_t2);
    cudaGetSymbolAddress((void**)&wkT, g_wkT);
    cudaGetSymbolAddress((void**)&kernT, g_kernT);
    cudaGetSymbolAddress((void**)&srcT, g_srcT);

    const dim3 tb(32, 8);

    // 0) layout prep: wkT[q][d], kernT[t][q], srcT[b][d][s]
    k_transpose<<<dim3(QQ / 32, DD / 32, 1), tb>>>(wk, wkT, DD, QQ, 0, 0);
    k_transpose<<<dim3(QQ / 32, QQ / 32, 1), tb>>>(kern, kernT, QQ, QQ, 0, 0);
    k_transpose<<<dim3(DD / 32, SS / 32, BB), tb>>>(src, srcT, SS, DD,
                                                    (long long)SS * DD, (long long)DD * SS);

    // 1) term2[b][s][q] = sum_d wq[s][d] * qry[b][q][d]  -> g_t2
    gemm_mma<<<dim3(QQ / BN, SS / BM, BB), 256>>>(
        wq, qry, t2, nullptr,
        DD, DD, QQ, DD,
        0LL, (long long)QQ * DD, (long long)SS * QQ, 0LL, 0);

    // 2) g_t1 = tanh( sum_d src[b][s][d]*wkT[q][d] + g_t2 )
    gemm_mma<<<dim3(QQ / BN, SS / BM, BB), 256>>>(
        src, wkT, t1, t2,
        DD, DD, QQ, DD,
        (long long)SS * DD, 0LL, (long long)SS * QQ, (long long)SS * QQ, 1);

    // 3) sim: g_t2[b][s][t] = sum_q g_t1[b][s][q] * kernT[t][q]
    gemm_mma<<<dim3(QQ / BN, SS / BM, BB), 256>>>(
        t1, kernT, t2, nullptr,
        QQ, QQ, QQ, QQ,
        (long long)SS * QQ, 0LL, (long long)SS * QQ, 0LL, 0);

    // 4) softmax rows of g_t2
    k_softmax<<<BB * SS, 256>>>();

    // 5) smT: g_t1[b][q][s] = g_t2[b][s][q]
    k_transpose<<<dim3(QQ / 32, SS / 32, BB), tb>>>(t2, t1, SS, QQ,
                                                    (long long)SS * QQ, (long long)QQ * SS);

    // 6) out[b][q][d] = sum_s smT[b][q][s] * srcT[b][d][s]
    gemm_mma<<<dim3(DD / BN, QQ / BM, BB), 256>>>(
        t1, srcT, out, nullptr,
        SS, SS, DD, SS,
        (long long)QQ * SS, (long long)DD * SS, (long long)QQ * DD, 0LL, 0);
}

// round 5
// speedup vs baseline: 6.0030x; 1.0126x over previous
#include <cuda_runtime.h>
#include <cstdint>
#include <math.h>

// Shapes (fixed)
#define BB 8
#define SS 2048
#define QQ 2048
#define DD 1024

// ---------------------------------------------------------------------------
// Scratch (device globals; no allocations allowed)
// All "C" buffers hold tf32-rounded values stored as f32 bit patterns.
// ---------------------------------------------------------------------------
__device__ float g_t1[(size_t)BB * SS * QQ];          // 134 MB  tanh(f_att), tf32
__device__ float g_t2[(size_t)BB * SS * QQ];          // 134 MB  sim / softmax (tf32 after softmax)
__device__ float g_wkT[(size_t)QQ * DD];              // 8 MB    wkT[q][d], tf32
__device__ float g_kernT[(size_t)QQ * QQ];            // 16 MB   kernT[t][q], tf32
__device__ float g_srcC[(size_t)BB * SS * DD];        // 64 MB   src, tf32
__device__ float g_qryC[(size_t)BB * QQ * DD];        // 64 MB   query, tf32
__device__ float g_wqC[(size_t)SS * DD];              // 8 MB    wq, tf32

// ---------------------------------------------------------------------------
// PTX helpers (baseline PTX only — sm_103 has no tcgen05 via this toolchain)
// ---------------------------------------------------------------------------
__device__ __forceinline__ uint32_t f32_to_tf32(float x) {
    uint32_t r;
    asm("cvt.rna.tf32.f32 %0, %1;" : "=r"(r) : "f"(x));
    return r;
}
__device__ __forceinline__ float round_tf32(float x) {
    return __uint_as_float(f32_to_tf32(x));
}

__device__ __forceinline__ void mma_tf32(float* d, const uint32_t* a, const uint32_t* b) {
    asm volatile(
        "mma.sync.aligned.m16n8k8.row.col.f32.tf32.tf32.f32 "
        "{%0,%1,%2,%3}, {%4,%5,%6,%7}, {%8,%9}, {%0,%1,%2,%3};\n"
        : "+f"(d[0]), "+f"(d[1]), "+f"(d[2]), "+f"(d[3])
        : "r"(a[0]), "r"(a[1]), "r"(a[2]), "r"(a[3]), "r"(b[0]), "r"(b[1]));
}

__device__ __forceinline__ void cp_async16(uint32_t smem_addr, const void* gptr) {
    asm volatile("cp.async.cg.shared.global [%0], [%1], 16;"
                 :: "r"(smem_addr), "l"(gptr));
}
#define CP_COMMIT() asm volatile("cp.async.commit_group;" ::: "memory")
#define CP_WAIT1()  asm volatile("cp.async.wait_group 1;" ::: "memory")

// ---------------------------------------------------------------------------
// Tile geometry: 128x128 CTA tile, BK=16, 256 threads (8 warps: 4(M) x 2(N)),
// warp tile 32x64, acc = 2x8 m16n8 fragments. Double-buffered cp.async.
// ---------------------------------------------------------------------------
#define BM 128
#define BN 128
#define BK 16
#define PAD 4
#define LDT (BK + PAD)    // MK layout: [row(m/n)][k], 20 floats
#define LDM 136           // KM layout: [k][m/n], 136 floats (8-bank stagger)

// ============================================================================
// Kernel A: merged f_att GEMM.  K = 2048 split in two 1024 halves:
//   half 0: A = srcC[b]  (m=s, k=d), B = wkT    (n=q, k=d)
//   half 1: A = wqC      (m=s, k=d), B = qryC[b](n=q, k=d)
// Epilogue: tanh, store tf32 bits -> g_t1.
// ============================================================================
__global__ void __launch_bounds__(256, 2)
gemm_fatt()
{
    __shared__ uint32_t As[2][BM][LDT];
    __shared__ uint32_t Bs[2][BN][LDT];

    const int tid = threadIdx.x;
    const int wid = tid >> 5;
    const int lane = tid & 31;
    const int warp_row = wid >> 1;
    const int warp_col = wid & 1;

    const int b  = blockIdx.z;
    const int m0 = blockIdx.y * BM;
    const int n0 = blockIdx.x * BN;

    const float* a_half[2] = { g_srcC + (size_t)b * SS * DD + (size_t)m0 * DD,
                               g_wqC  + (size_t)m0 * DD };
    const float* b_half[2] = { g_wkT  + (size_t)n0 * DD,
                               g_qryC + (size_t)b * QQ * DD + (size_t)n0 * DD };

    const int l_row0 = tid >> 2;            // 0..63 (+64)
    const int l_c4   = (tid & 3) * 4;

    float acc[2][8][4];
#pragma unroll
    for (int i = 0; i < 2; i++)
#pragma unroll
        for (int j = 0; j < 8; j++)
#pragma unroll
            for (int r = 0; r < 4; r++) acc[i][j][r] = 0.f;

    const int ntiles = 2048 / BK;   // 128

    // prologue
    {
        const float* ap = a_half[0] + (size_t)l_row0 * DD + l_c4;
        const float* bp = b_half[0] + (size_t)l_row0 * DD + l_c4;
        cp_async16((uint32_t)__cvta_generic_to_shared(&As[0][l_row0][l_c4]), ap);
        cp_async16((uint32_t)__cvta_generic_to_shared(&As[0][l_row0 + 64][l_c4]),
                   ap + (size_t)64 * DD);
        cp_async16((uint32_t)__cvta_generic_to_shared(&Bs[0][l_row0][l_c4]), bp);
        cp_async16((uint32_t)__cvta_generic_to_shared(&Bs[0][l_row0 + 64][l_c4]),
                   bp + (size_t)64 * DD);
        CP_COMMIT();
    }

    const int a_row = warp_row * 32 + (lane >> 2);
    const int b_row = warp_col * 64 + (lane >> 2);
    const int kq    = lane & 3;

    for (int t = 0; t < ntiles; t++) {
        const int cur = t & 1;
        const int nxt = cur ^ 1;

        if (t + 1 < ntiles) {
            const int tt = t + 1;
            const int h  = tt >> 6;               // half select
            const int k0 = (tt & 63) * BK;
            const float* ap = a_half[h] + (size_t)l_row0 * DD + k0 + l_c4;
            const float* bp = b_half[h] + (size_t)l_row0 * DD + k0 + l_c4;
            cp_async16((uint32_t)__cvta_generic_to_shared(&As[nxt][l_row0][l_c4]), ap);
            cp_async16((uint32_t)__cvta_generic_to_shared(&As[nxt][l_row0 + 64][l_c4]),
                       ap + (size_t)64 * DD);
            cp_async16((uint32_t)__cvta_generic_to_shared(&Bs[nxt][l_row0][l_c4]), bp);
            cp_async16((uint32_t)__cvta_generic_to_shared(&Bs[nxt][l_row0 + 64][l_c4]),
                       bp + (size_t)64 * DD);
        }
        CP_COMMIT();
        CP_WAIT1();
        __syncthreads();

#pragma unroll
        for (int ks = 0; ks < 2; ks++) {
            const int kb = ks * 8 + kq;
            uint32_t afr[2][4];
#pragma unroll
            for (int i = 0; i < 2; i++) {
                const int r = a_row + i * 16;
                afr[i][0] = As[cur][r][kb];
                afr[i][1] = As[cur][r + 8][kb];
                afr[i][2] = As[cur][r][kb + 4];
                afr[i][3] = As[cur][r + 8][kb + 4];
            }
            uint32_t bfr[8][2];
#pragma unroll
            for (int j = 0; j < 8; j++) {
                const int r = b_row + j * 8;
                bfr[j][0] = Bs[cur][r][kb];
                bfr[j][1] = Bs[cur][r][kb + 4];
            }
#pragma unroll
            for (int i = 0; i < 2; i++)
#pragma unroll
                for (int j = 0; j < 8; j++)
                    mma_tf32(acc[i][j], afr[i], bfr[j]);
        }
        __syncthreads();
    }

    float* Cb = g_t1 + (size_t)b * SS * QQ;
#pragma unroll
    for (int i = 0; i < 2; i++) {
        const int row0 = m0 + warp_row * 32 + i * 16 + (lane >> 2);
#pragma unroll
        for (int j = 0; j < 8; j++) {
            const int col = n0 + warp_col * 64 + j * 8 + 2 * (lane & 3);
#pragma unroll
            for (int r = 0; r < 2; r++) {
                const size_t off = (size_t)(row0 + r * 8) * QQ + col;
                float2 v;
                v.x = round_tf32(tanhf(acc[i][j][r * 2 + 0]));
                v.y = round_tf32(tanhf(acc[i][j][r * 2 + 1]));
                *reinterpret_cast<float2*>(Cb + off) = v;
            }
        }
    }
}

// ============================================================================
// Kernel B: generic MK-layout GEMM (GEMM3): C[b][m][n] = sum_k A[m][k]*B[n][k]
// A = g_t1 (tf32 bits), B = g_kernT (tf32 bits), C = g_t2 raw f32.
// ============================================================================
__global__ void __launch_bounds__(256, 2)
gemm_sim()
{
    __shared__ uint32_t As[2][BM][LDT];
    __shared__ uint32_t Bs[2][BN][LDT];

    const int tid = threadIdx.x;
    const int wid = tid >> 5;
    const int lane = tid & 31;
    const int warp_row = wid >> 1;
    const int warp_col = wid & 1;

    const int b  = blockIdx.z;
    const int m0 = blockIdx.y * BM;
    const int n0 = blockIdx.x * BN;

    const float* Ab = g_t1 + (size_t)b * SS * QQ + (size_t)m0 * QQ;
    const float* Bb = g_kernT + (size_t)n0 * QQ;

    const int l_row0 = tid >> 2;
    const int l_c4   = (tid & 3) * 4;

    float acc[2][8][4];
#pragma unroll
    for (int i = 0; i < 2; i++)
#pragma unroll
        for (int j = 0; j < 8; j++)
#pragma unroll
            for (int r = 0; r < 4; r++) acc[i][j][r] = 0.f;

    const int ntiles = QQ / BK;   // 128

    {
        const float* ap = Ab + (size_t)l_row0 * QQ + l_c4;
        const float* bp = Bb + (size_t)l_row0 * QQ + l_c4;
        cp_async16((uint32_t)__cvta_generic_to_shared(&As[0][l_row0][l_c4]), ap);
        cp_async16((uint32_t)__cvta_generic_to_shared(&As[0][l_row0 + 64][l_c4]),
                   ap + (size_t)64 * QQ);
        cp_async16((uint32_t)__cvta_generic_to_shared(&Bs[0][l_row0][l_c4]), bp);
        cp_async16((uint32_t)__cvta_generic_to_shared(&Bs[0][l_row0 + 64][l_c4]),
                   bp + (size_t)64 * QQ);
        CP_COMMIT();
    }

    const int a_row = warp_row * 32 + (lane >> 2);
    const int b_row = warp_col * 64 + (lane >> 2);
    const int kq    = lane & 3;

    for (int t = 0; t < ntiles; t++) {
        const int cur = t & 1;
        const int nxt = cur ^ 1;

        if (t + 1 < ntiles) {
            const int k0 = (t + 1) * BK;
            const float* ap = Ab + (size_t)l_row0 * QQ + k0 + l_c4;
            const float* bp = Bb + (size_t)l_row0 * QQ + k0 + l_c4;
            cp_async16((uint32_t)__cvta_generic_to_shared(&As[nxt][l_row0][l_c4]), ap);
            cp_async16((uint32_t)__cvta_generic_to_shared(&As[nxt][l_row0 + 64][l_c4]),
                       ap + (size_t)64 * QQ);
            cp_async16((uint32_t)__cvta_generic_to_shared(&Bs[nxt][l_row0][l_c4]), bp);
            cp_async16((uint32_t)__cvta_generic_to_shared(&Bs[nxt][l_row0 + 64][l_c4]),
                       bp + (size_t)64 * QQ);
        }
        CP_COMMIT();
        CP_WAIT1();
        __syncthreads();

#pragma unroll
        for (int ks = 0; ks < 2; ks++) {
            const int kb = ks * 8 + kq;
            uint32_t afr[2][4];
#pragma unroll
            for (int i = 0; i < 2; i++) {
                const int r = a_row + i * 16;
                afr[i][0] = As[cur][r][kb];
                afr[i][1] = As[cur][r + 8][kb];
                afr[i][2] = As[cur][r][kb + 4];
                afr[i][3] = As[cur][r + 8][kb + 4];
            }
            uint32_t bfr[8][2];
#pragma unroll
            for (int j = 0; j < 8; j++) {
                const int r = b_row + j * 8;
                bfr[j][0] = Bs[cur][r][kb];
                bfr[j][1] = Bs[cur][r][kb + 4];
            }
#pragma unroll
            for (int i = 0; i < 2; i++)
#pragma unroll
                for (int j = 0; j < 8; j++)
                    mma_tf32(acc[i][j], afr[i], bfr[j]);
        }
        __syncthreads();
    }

    float* Cb = g_t2 + (size_t)b * SS * QQ;
#pragma unroll
    for (int i = 0; i < 2; i++) {
        const int row0 = m0 + warp_row * 32 + i * 16 + (lane >> 2);
#pragma unroll
        for (int j = 0; j < 8; j++) {
            const int col = n0 + warp_col * 64 + j * 8 + 2 * (lane & 3);
#pragma unroll
            for (int r = 0; r < 2; r++) {
                const size_t off = (size_t)(row0 + r * 8) * QQ + col;
                float2 v;
                v.x = acc[i][j][r * 2 + 0];
                v.y = acc[i][j][r * 2 + 1];
                *reinterpret_cast<float2*>(Cb + off) = v;
            }
        }
    }
}

// ============================================================================
// Kernel C: KM-layout GEMM (GEMM4): out[b][q][d] = sum_s sm[b][s][q]*src[b][s][d]
// Both operands are k(=s)-major in gmem -> straight cp.async into [k][m] tiles.
//   A = g_t2 (softmax probs, tf32 bits), lda = QQ
//   B = g_srcC,                          ldb = DD
// ============================================================================
__global__ void __launch_bounds__(256, 2)
gemm_out(float* __restrict__ C)
{
    __shared__ uint32_t As[2][BK][LDM];
    __shared__ uint32_t Bs[2][BK][LDM];

    const int tid = threadIdx.x;
    const int wid = tid >> 5;
    const int lane = tid & 31;
    const int warp_row = wid >> 1;
    const int warp_col = wid & 1;

    const int b  = blockIdx.z;
    const int m0 = blockIdx.y * BM;   // q
    const int n0 = blockIdx.x * BN;   // d

    const float* Ab = g_t2 + (size_t)b * SS * QQ + m0;    // [k][m] walk k rows
    const float* Bb = g_srcC + (size_t)b * SS * DD + n0;  // [k][n]

    // loader: 512 float4 chunks per operand tile; 2 per thread
    const int lr0 = tid >> 4;          // rows 0..15
    const int lc0 = (tid & 15) * 4;    // cols 0..60 step 4 (first 64 floats)
    // second chunk covers cols 64..127:
    const int lc1 = lc0 + 64;

    float acc[2][8][4];
#pragma unroll
    for (int i = 0; i < 2; i++)
#pragma unroll
        for (int j = 0; j < 8; j++)
#pragma unroll
            for (int r = 0; r < 4; r++) acc[i][j][r] = 0.f;

    const int ntiles = SS / BK;   // 128

    {
        const float* ap = Ab + (size_t)lr0 * QQ;
        const float* bp = Bb + (size_t)lr0 * DD;
        cp_async16((uint32_t)__cvta_generic_to_shared(&As[0][lr0][lc0]), ap + lc0);
        cp_async16((uint32_t)__cvta_generic_to_shared(&As[0][lr0][lc1]), ap + lc1);
        cp_async16((uint32_t)__cvta_generic_to_shared(&Bs[0][lr0][lc0]), bp + lc0);
        cp_async16((uint32_t)__cvta_generic_to_shared(&Bs[0][lr0][lc1]), bp + lc1);
        CP_COMMIT();
    }

    const int a_row = warp_row * 32 + (lane >> 2);
    const int b_row = warp_col * 64 + (lane >> 2);
    const int kq    = lane & 3;

    for (int t = 0; t < ntiles; t++) {
        const int cur = t & 1;
        const int nxt = cur ^ 1;

        if (t + 1 < ntiles) {
            const int k0 = (t + 1) * BK;
            const float* ap = Ab + (size_t)(k0 + lr0) * QQ;
            const float* bp = Bb + (size_t)(k0 + lr0) * DD;
            cp_async16((uint32_t)__cvta_generic_to_shared(&As[nxt][lr0][lc0]), ap + lc0);
            cp_async16((uint32_t)__cvta_generic_to_shared(&As[nxt][lr0][lc1]), ap + lc1);
            cp_async16((uint32_t)__cvta_generic_to_shared(&Bs[nxt][lr0][lc0]), bp + lc0);
            cp_async16((uint32_t)__cvta_generic_to_shared(&Bs[nxt][lr0][lc1]), bp + lc1);
        }
        CP_COMMIT();
        CP_WAIT1();
        __syncthreads();

#pragma unroll
        for (int ks = 0; ks < 2; ks++) {
            const int kb = ks * 8 + kq;
            uint32_t afr[2][4];
#pragma unroll
            for (int i = 0; i < 2; i++) {
                const int r = a_row + i * 16;
                afr[i][0] = As[cur][kb][r];
                afr[i][1] = As[cur][kb][r + 8];
                afr[i][2] = As[cur][kb + 4][r];
                afr[i][3] = As[cur][kb + 4][r + 8];
            }
            uint32_t bfr[8][2];
#pragma unroll
            for (int j = 0; j < 8; j++) {
                const int r = b_row + j * 8;
                bfr[j][0] = Bs[cur][kb][r];
                bfr[j][1] = Bs[cur][kb + 4][r];
            }
#pragma unroll
            for (int i = 0; i < 2; i++)
#pragma unroll
                for (int j = 0; j < 8; j++)
                    mma_tf32(acc[i][j], afr[i], bfr[j]);
        }
        __syncthreads();
    }

    float* Cb = C + (size_t)b * QQ * DD;
#pragma unroll
    for (int i = 0; i < 2; i++) {
        const int row0 = m0 + warp_row * 32 + i * 16 + (lane >> 2);
#pragma unroll
        for (int j = 0; j < 8; j++) {
            const int col = n0 + warp_col * 64 + j * 8 + 2 * (lane & 3);
#pragma unroll
            for (int r = 0; r < 2; r++) {
                const size_t off = (size_t)(row0 + r * 8) * DD + col;
                float2 v;
                v.x = acc[i][j][r * 2 + 0];
                v.y = acc[i][j][r * 2 + 1];
                *reinterpret_cast<float2*>(Cb + off) = v;
            }
        }
    }
}

// ---------------------------------------------------------------------------
// Elementwise f32 -> tf32-rounded f32 (vectorized)
// ---------------------------------------------------------------------------
__global__ void k_cvt(const float4* __restrict__ in, float4* __restrict__ out, int n4)
{
    int i = blockIdx.x * blockDim.x + threadIdx.x;
    if (i < n4) {
        float4 v = in[i];
        v.x = round_tf32(v.x); v.y = round_tf32(v.y);
        v.z = round_tf32(v.z); v.w = round_tf32(v.w);
        out[i] = v;
    }
}

// ---------------------------------------------------------------------------
// Tiled transpose with tf32 rounding: out[c][r] = tf32(in[r][c])
// ---------------------------------------------------------------------------
__global__ void k_transpose(const float* __restrict__ in, float* __restrict__ out,
                            int R, int C)
{
    __shared__ float tile[32][33];
    const int c0 = blockIdx.x * 32;
    const int r0 = blockIdx.y * 32;

#pragma unroll
    for (int i = threadIdx.y; i < 32; i += 8)
        tile[i][threadIdx.x] = in[(size_t)(r0 + i) * C + c0 + threadIdx.x];
    __syncthreads();
#pragma unroll
    for (int i = threadIdx.y; i < 32; i += 8)
        out[(size_t)(c0 + i) * R + r0 + threadIdx.x] = round_tf32(tile[threadIdx.x][i]);
}

// ---------------------------------------------------------------------------
// In-place row softmax on g_t2 (B*S rows of length QQ); output tf32-rounded.
// ---------------------------------------------------------------------------
__global__ void k_softmax()
{
    float* p = g_t2 + (size_t)blockIdx.x * QQ;
    const int tid = threadIdx.x;  // 256

    __shared__ float red[32];

    float m = -INFINITY;
    for (int i = tid; i < QQ; i += 256) m = fmaxf(m, p[i]);
#pragma unroll
    for (int o = 16; o > 0; o >>= 1) m = fmaxf(m, __shfl_xor_sync(0xffffffffu, m, o));
    if ((tid & 31) == 0) red[tid >> 5] = m;
    __syncthreads();
    if (tid < 32) {
        float v = (tid < 8) ? red[tid] : -INFINITY;
#pragma unroll
        for (int o = 4; o > 0; o >>= 1) v = fmaxf(v, __shfl_xor_sync(0xffffffffu, v, o));
        red[tid] = v;
    }
    __syncthreads();
    m = red[0];
    __syncthreads();

    float sum = 0.f;
    for (int i = tid; i < QQ; i += 256) {
        float e = __expf(p[i] - m);
        p[i] = e;
        sum += e;
    }
#pragma unroll
    for (int o = 16; o > 0; o >>= 1) sum += __shfl_xor_sync(0xffffffffu, sum, o);
    if ((tid & 31) == 0) red[tid >> 5] = sum;
    __syncthreads();
    if (tid < 32) {
        float v = (tid < 8) ? red[tid] : 0.f;
#pragma unroll
        for (int o = 4; o > 0; o >>= 1) v += __shfl_xor_sync(0xffffffffu, v, o);
        red[tid] = v;
    }
    __syncthreads();
    const float inv = 1.0f / red[0];

    for (int i = tid; i < QQ; i += 256) p[i] = round_tf32(p[i] * inv);
}

// ---------------------------------------------------------------------------
// Launcher
// ---------------------------------------------------------------------------
extern "C" void kernel_launch(void* const* d_in, const int* in_sizes, int n_in,
                              void* d_out, int out_size)
{
    const float* src  = (const float*)d_in[0];  // (B,S,D)
    const float* qry  = (const float*)d_in[1];  // (B,Q,D)
    const float* kern = (const float*)d_in[2];  // (Q,T)
    const float* wk   = (const float*)d_in[3];  // (D,Q)
    const float* wq   = (const float*)d_in[4];  // (S,D)
    float* out = (float*)d_out;                 // (B,Q,D)

    float *wkT, *kernT, *srcC, *qryC, *wqC;
    cudaGetSymbolAddress((void**)&wkT, g_wkT);
    cudaGetSymbolAddress((void**)&kernT, g_kernT);
    cudaGetSymbolAddress((void**)&srcC, g_srcC);
    cudaGetSymbolAddress((void**)&qryC, g_qryC);
    cudaGetSymbolAddress((void**)&wqC, g_wqC);

    // 0) operand prep: tf32-round everything feeding a GEMM
    {
        int n4;
        n4 = (BB * SS * DD) / 4;
        k_cvt<<<(n4 + 255) / 256, 256>>>((const float4*)src, (float4*)srcC, n4);
        n4 = (BB * QQ * DD) / 4;
        k_cvt<<<(n4 + 255) / 256, 256>>>((const float4*)qry, (float4*)qryC, n4);
        n4 = (SS * DD) / 4;
        k_cvt<<<(n4 + 255) / 256, 256>>>((const float4*)wq, (float4*)wqC, n4);
    }
    const dim3 tb(32, 8);
    k_transpose<<<dim3(QQ / 32, DD / 32), tb>>>(wk, wkT, DD, QQ);
    k_transpose<<<dim3(QQ / 32, QQ / 32), tb>>>(kern, kernT, QQ, QQ);

    // 1) merged f_att: t1 = tanh(src@wk + wq@qry^T), tf32 output
    gemm_fatt<<<dim3(QQ / BN, SS / BM, BB), 256>>>();

    // 2) sim: t2 = t1 @ kernT
    gemm_sim<<<dim3(QQ / BN, SS / BM, BB), 256>>>();

    // 3) softmax rows of t2 (tf32 output)
    k_softmax<<<BB * SS, 256>>>();

    // 4) out = sm^T @ src  (KM-layout GEMM, no transposes needed)
    gemm_out<<<dim3(DD / BN, QQ / BM, BB), 256>>>(out);
}

// round 6
// speedup vs baseline: 7.2152x; 1.2019x over previous
#include <cuda_runtime.h>
#include <cstdint>
#include <math.h>

// Shapes (fixed)
#define BB 8
#define SS 2048
#define QQ 2048
#define DD 1024

// ---------------------------------------------------------------------------
// Scratch (device globals). "C" buffers hold tf32-rounded f32 bit patterns.
// ---------------------------------------------------------------------------
__device__ float g_t1[(size_t)BB * SS * QQ];          // tanh(f_att), tf32
__device__ float g_t2[(size_t)BB * SS * QQ];          // sim / softmax probs
__device__ float g_wkT[(size_t)QQ * DD];              // wkT[q][d], tf32
__device__ float g_kernT[(size_t)QQ * QQ];            // kernT[t][q], tf32
__device__ float g_srcC[(size_t)BB * SS * DD];        // src, tf32
__device__ float g_qryC[(size_t)BB * QQ * DD];        // query, tf32
__device__ float g_wqC[(size_t)SS * DD];              // wq, tf32

// ---------------------------------------------------------------------------
// PTX helpers (baseline PTX only)
// ---------------------------------------------------------------------------
__device__ __forceinline__ uint32_t f32_to_tf32(float x) {
    uint32_t r;
    asm("cvt.rna.tf32.f32 %0, %1;" : "=r"(r) : "f"(x));
    return r;
}
__device__ __forceinline__ float round_tf32(float x) {
    return __uint_as_float(f32_to_tf32(x));
}

__device__ __forceinline__ void mma_tf32(float* d, const uint32_t* a, const uint32_t* b) {
    asm volatile(
        "mma.sync.aligned.m16n8k8.row.col.f32.tf32.tf32.f32 "
        "{%0,%1,%2,%3}, {%4,%5,%6,%7}, {%8,%9}, {%0,%1,%2,%3};\n"
        : "+f"(d[0]), "+f"(d[1]), "+f"(d[2]), "+f"(d[3])
        : "r"(a[0]), "r"(a[1]), "r"(a[2]), "r"(a[3]), "r"(b[0]), "r"(b[1]));
}

__device__ __forceinline__ void ldsm_x4(uint32_t* r, uint32_t saddr) {
    asm volatile("ldmatrix.sync.aligned.m8n8.x4.shared.b16 {%0,%1,%2,%3}, [%4];"
                 : "=r"(r[0]), "=r"(r[1]), "=r"(r[2]), "=r"(r[3])
                 : "r"(saddr));
}

__device__ __forceinline__ void cp_async16(uint32_t smem_addr, const void* gptr) {
    asm volatile("cp.async.cg.shared.global [%0], [%1], 16;"
                 :: "r"(smem_addr), "l"(gptr));
}
#define CP_COMMIT() asm volatile("cp.async.commit_group;" ::: "memory")
#define CP_WAIT0()  asm volatile("cp.async.wait_group 0;" ::: "memory")

// ---------------------------------------------------------------------------
// Tile geometry: 128x128 CTA, BK=16, 256 threads (8 warps = 4(M) x 2(N)),
// warp tile 32x64. Double-buffered cp.async, single sync per K-tile.
// ---------------------------------------------------------------------------
#define BM 128
#define BN 128
#define BK 16
#define PAD 4
#define LDT (BK + PAD)               // 20 floats/row (MK layout)
#define LDM 136                      // KM layout row width
#define STAGE_BYTES (BM * LDT * 4)   // 10240 bytes per tile stage

// per-thread LDSM source offsets (bytes within one tile stage)
struct LdsmOffs {
    uint32_t a[2];   // A fragments i=0,1 (rows warp_row*32 + i*16 ..)
    uint32_t b[4];   // B fragment pairs jp=0..3 (cols warp_col*64 + jp*16 ..)
};

__device__ __forceinline__ LdsmOffs make_offs(int warp_row, int warp_col, int lane) {
    LdsmOffs o;
    const int sel = lane >> 3;       // 0..3 matrix select
    const int rin = lane & 7;        // row within matrix
#pragma unroll
    for (int i = 0; i < 2; i++) {
        int r = warp_row * 32 + i * 16 + (sel & 1) * 8 + rin;
        int c = (sel >> 1) * 4;
        o.a[i] = (uint32_t)((r * LDT + c) * 4);
    }
#pragma unroll
    for (int jp = 0; jp < 4; jp++) {
        int n = warp_col * 64 + jp * 16 + (sel >> 1) * 8 + rin;
        int c = (sel & 1) * 4;
        o.b[jp] = (uint32_t)((n * LDT + c) * 4);
    }
    return o;
}

// one k8 step: 6 LDSM.x4 + 16 MMA
__device__ __forceinline__ void mma_step(float acc[2][8][4],
                                         uint32_t aBase, uint32_t bBase,
                                         const LdsmOffs& o, int ks) {
    const uint32_t kadd = ks * 32;   // 8 floats = 32 bytes
    uint32_t afr[2][4];
    ldsm_x4(afr[0], aBase + o.a[0] + kadd);
    ldsm_x4(afr[1], aBase + o.a[1] + kadd);
    uint32_t bfr[4][4];
#pragma unroll
    for (int jp = 0; jp < 4; jp++)
        ldsm_x4(bfr[jp], bBase + o.b[jp] + kadd);
#pragma unroll
    for (int i = 0; i < 2; i++)
#pragma unroll
        for (int j = 0; j < 8; j++)
            mma_tf32(acc[i][j], afr[i], &bfr[j >> 1][(j & 1) * 2]);
}

// ============================================================================
// Kernel A: merged f_att GEMM. K=2048 as two 1024 halves:
//   half 0: A=srcC[b], B=wkT ; half 1: A=wqC, B=qryC[b]
// Epilogue: tanh, tf32 store -> g_t1.
// ============================================================================
__global__ void __launch_bounds__(256, 2)
gemm_fatt()
{
    __shared__ uint32_t As[2][BM][LDT];
    __shared__ uint32_t Bs[2][BN][LDT];

    const int tid = threadIdx.x;
    const int wid = tid >> 5;
    const int lane = tid & 31;
    const int warp_row = wid >> 1;
    const int warp_col = wid & 1;

    const int b  = blockIdx.z;
    const int m0 = blockIdx.y * BM;
    const int n0 = blockIdx.x * BN;

    const float* a_half[2] = { g_srcC + (size_t)b * SS * DD + (size_t)m0 * DD,
                               g_wqC  + (size_t)m0 * DD };
    const float* b_half[2] = { g_wkT  + (size_t)n0 * DD,
                               g_qryC + (size_t)b * QQ * DD + (size_t)n0 * DD };

    const int l_row0 = tid >> 2;
    const int l_c4   = (tid & 3) * 4;

    const uint32_t asBase = (uint32_t)__cvta_generic_to_shared(&As[0][0][0]);
    const uint32_t bsBase = (uint32_t)__cvta_generic_to_shared(&Bs[0][0][0]);
    const uint32_t ldOffA = (uint32_t)((l_row0 * LDT + l_c4) * 4);
    const uint32_t ldOffA2 = ldOffA + (uint32_t)(64 * LDT * 4);
    const LdsmOffs offs = make_offs(warp_row, warp_col, lane);

    float acc[2][8][4];
#pragma unroll
    for (int i = 0; i < 2; i++)
#pragma unroll
        for (int j = 0; j < 8; j++)
#pragma unroll
            for (int r = 0; r < 4; r++) acc[i][j][r] = 0.f;

    const int ntiles = 2048 / BK;    // 128

    // prologue: tile 0
    {
        const float* ap = a_half[0] + (size_t)l_row0 * DD + l_c4;
        const float* bp = b_half[0] + (size_t)l_row0 * DD + l_c4;
        cp_async16(asBase + ldOffA, ap);
        cp_async16(asBase + ldOffA2, ap + (size_t)64 * DD);
        cp_async16(bsBase + ldOffA, bp);
        cp_async16(bsBase + ldOffA2, bp + (size_t)64 * DD);
        CP_COMMIT();
    }

    for (int t = 0; t < ntiles; t++) {
        const uint32_t curOff = (uint32_t)(t & 1) * STAGE_BYTES;
        const uint32_t nxtOff = curOff ^ STAGE_BYTES;

        CP_WAIT0();
        __syncthreads();

        if (t + 1 < ntiles) {
            const int tt = t + 1;
            const int h  = tt >> 6;
            const int k0 = (tt & 63) * BK;
            const float* ap = a_half[h] + (size_t)l_row0 * DD + k0 + l_c4;
            const float* bp = b_half[h] + (size_t)l_row0 * DD + k0 + l_c4;
            cp_async16(asBase + nxtOff + ldOffA, ap);
            cp_async16(asBase + nxtOff + ldOffA2, ap + (size_t)64 * DD);
            cp_async16(bsBase + nxtOff + ldOffA, bp);
            cp_async16(bsBase + nxtOff + ldOffA2, bp + (size_t)64 * DD);
            CP_COMMIT();
        }

        mma_step(acc, asBase + curOff, bsBase + curOff, offs, 0);
        mma_step(acc, asBase + curOff, bsBase + curOff, offs, 1);
    }

    float* Cb = g_t1 + (size_t)b * SS * QQ;
#pragma unroll
    for (int i = 0; i < 2; i++) {
        const int row0 = m0 + warp_row * 32 + i * 16 + (lane >> 2);
#pragma unroll
        for (int j = 0; j < 8; j++) {
            const int col = n0 + warp_col * 64 + j * 8 + 2 * (lane & 3);
#pragma unroll
            for (int r = 0; r < 2; r++) {
                const size_t off = (size_t)(row0 + r * 8) * QQ + col;
                float2 v;
                v.x = round_tf32(tanhf(acc[i][j][r * 2 + 0]));
                v.y = round_tf32(tanhf(acc[i][j][r * 2 + 1]));
                *reinterpret_cast<float2*>(Cb + off) = v;
            }
        }
    }
}

// ============================================================================
// Kernel B: sim GEMM. C[b][m][n] = sum_k t1[b][m][k] * kernT[n][k], K=2048.
// ============================================================================
__global__ void __launch_bounds__(256, 2)
gemm_sim()
{
    __shared__ uint32_t As[2][BM][LDT];
    __shared__ uint32_t Bs[2][BN][LDT];

    const int tid = threadIdx.x;
    const int wid = tid >> 5;
    const int lane = tid & 31;
    const int warp_row = wid >> 1;
    const int warp_col = wid & 1;

    const int b  = blockIdx.z;
    const int m0 = blockIdx.y * BM;
    const int n0 = blockIdx.x * BN;

    const float* Ab = g_t1 + (size_t)b * SS * QQ + (size_t)m0 * QQ;
    const float* Bb = g_kernT + (size_t)n0 * QQ;

    const int l_row0 = tid >> 2;
    const int l_c4   = (tid & 3) * 4;

    const uint32_t asBase = (uint32_t)__cvta_generic_to_shared(&As[0][0][0]);
    const uint32_t bsBase = (uint32_t)__cvta_generic_to_shared(&Bs[0][0][0]);
    const uint32_t ldOffA = (uint32_t)((l_row0 * LDT + l_c4) * 4);
    const uint32_t ldOffA2 = ldOffA + (uint32_t)(64 * LDT * 4);
    const LdsmOffs offs = make_offs(warp_row, warp_col, lane);

    float acc[2][8][4];
#pragma unroll
    for (int i = 0; i < 2; i++)
#pragma unroll
        for (int j = 0; j < 8; j++)
#pragma unroll
            for (int r = 0; r < 4; r++) acc[i][j][r] = 0.f;

    const int ntiles = QQ / BK;    // 128

    {
        const float* ap = Ab + (size_t)l_row0 * QQ + l_c4;
        const float* bp = Bb + (size_t)l_row0 * QQ + l_c4;
        cp_async16(asBase + ldOffA, ap);
        cp_async16(asBase + ldOffA2, ap + (size_t)64 * QQ);
        cp_async16(bsBase + ldOffA, bp);
        cp_async16(bsBase + ldOffA2, bp + (size_t)64 * QQ);
        CP_COMMIT();
    }

    for (int t = 0; t < ntiles; t++) {
        const uint32_t curOff = (uint32_t)(t & 1) * STAGE_BYTES;
        const uint32_t nxtOff = curOff ^ STAGE_BYTES;

        CP_WAIT0();
        __syncthreads();

        if (t + 1 < ntiles) {
            const int k0 = (t + 1) * BK;
            const float* ap = Ab + (size_t)l_row0 * QQ + k0 + l_c4;
            const float* bp = Bb + (size_t)l_row0 * QQ + k0 + l_c4;
            cp_async16(asBase + nxtOff + ldOffA, ap);
            cp_async16(asBase + nxtOff + ldOffA2, ap + (size_t)64 * QQ);
            cp_async16(bsBase + nxtOff + ldOffA, bp);
            cp_async16(bsBase + nxtOff + ldOffA2, bp + (size_t)64 * QQ);
            CP_COMMIT();
        }

        mma_step(acc, asBase + curOff, bsBase + curOff, offs, 0);
        mma_step(acc, asBase + curOff, bsBase + curOff, offs, 1);
    }

    float* Cb = g_t2 + (size_t)b * SS * QQ;
#pragma unroll
    for (int i = 0; i < 2; i++) {
        const int row0 = m0 + warp_row * 32 + i * 16 + (lane >> 2);
#pragma unroll
        for (int j = 0; j < 8; j++) {
            const int col = n0 + warp_col * 64 + j * 8 + 2 * (lane & 3);
#pragma unroll
            for (int r = 0; r < 2; r++) {
                const size_t off = (size_t)(row0 + r * 8) * QQ + col;
                float2 v;
                v.x = acc[i][j][r * 2 + 0];
                v.y = acc[i][j][r * 2 + 1];
                *reinterpret_cast<float2*>(Cb + off) = v;
            }
        }
    }
}

// ============================================================================
// Kernel C: out[b][q][d] = sum_s sm[b][s][q] * src[b][s][d]  (KM layout, K=s)
// ============================================================================
__global__ void __launch_bounds__(256, 2)
gemm_out(float* __restrict__ C)
{
    __shared__ uint32_t As[2][BK][LDM];
    __shared__ uint32_t Bs[2][BK][LDM];

    const int tid = threadIdx.x;
    const int wid = tid >> 5;
    const int lane = tid & 31;
    const int warp_row = wid >> 1;
    const int warp_col = wid & 1;

    const int b  = blockIdx.z;
    const int m0 = blockIdx.y * BM;   // q
    const int n0 = blockIdx.x * BN;   // d

    const float* Ab = g_t2 + (size_t)b * SS * QQ + m0;
    const float* Bb = g_srcC + (size_t)b * SS * DD + n0;

    const int lr0 = tid >> 4;
    const int lc0 = (tid & 15) * 4;
    const int lc1 = lc0 + 64;

    const uint32_t asBase = (uint32_t)__cvta_generic_to_shared(&As[0][0][0]);
    const uint32_t bsBase = (uint32_t)__cvta_generic_to_shared(&Bs[0][0][0]);
    const uint32_t stageB = (uint32_t)(BK * LDM * 4);
    const uint32_t w0 = (uint32_t)((lr0 * LDM + lc0) * 4);
    const uint32_t w1 = (uint32_t)((lr0 * LDM + lc1) * 4);

    float acc[2][8][4];
#pragma unroll
    for (int i = 0; i < 2; i++)
#pragma unroll
        for (int j = 0; j < 8; j++)
#pragma unroll
            for (int r = 0; r < 4; r++) acc[i][j][r] = 0.f;

    const int ntiles = SS / BK;

    {
        const float* ap = Ab + (size_t)lr0 * QQ;
        const float* bp = Bb + (size_t)lr0 * DD;
        cp_async16(asBase + w0, ap + lc0);
        cp_async16(asBase + w1, ap + lc1);
        cp_async16(bsBase + w0, bp + lc0);
        cp_async16(bsBase + w1, bp + lc1);
        CP_COMMIT();
    }

    const int a_row = warp_row * 32 + (lane >> 2);
    const int b_row = warp_col * 64 + (lane >> 2);
    const int kq    = lane & 3;

    for (int t = 0; t < ntiles; t++) {
        const int cur = t & 1;
        const uint32_t nxtOff = (uint32_t)(cur ^ 1) * stageB;

        CP_WAIT0();
        __syncthreads();

        if (t + 1 < ntiles) {
            const int k0 = (t + 1) * BK;
            const float* ap = Ab + (size_t)(k0 + lr0) * QQ;
            const float* bp = Bb + (size_t)(k0 + lr0) * DD;
            cp_async16(asBase + nxtOff + w0, ap + lc0);
            cp_async16(asBase + nxtOff + w1, ap + lc1);
            cp_async16(bsBase + nxtOff + w0, bp + lc0);
            cp_async16(bsBase + nxtOff + w1, bp + lc1);
            CP_COMMIT();
        }

#pragma unroll
        for (int ks = 0; ks < 2; ks++) {
            const int kb = ks * 8 + kq;
            uint32_t afr[2][4];
#pragma unroll
            for (int i = 0; i < 2; i++) {
                const int r = a_row + i * 16;
                afr[i][0] = As[cur][kb][r];
                afr[i][1] = As[cur][kb][r + 8];
                afr[i][2] = As[cur][kb + 4][r];
                afr[i][3] = As[cur][kb + 4][r + 8];
            }
            uint32_t bfr[8][2];
#pragma unroll
            for (int j = 0; j < 8; j++) {
                const int r = b_row + j * 8;
                bfr[j][0] = Bs[cur][kb][r];
                bfr[j][1] = Bs[cur][kb + 4][r];
            }
#pragma unroll
            for (int i = 0; i < 2; i++)
#pragma unroll
                for (int j = 0; j < 8; j++)
                    mma_tf32(acc[i][j], afr[i], bfr[j]);
        }
    }

    float* Cb = C + (size_t)b * QQ * DD;
#pragma unroll
    for (int i = 0; i < 2; i++) {
        const int row0 = m0 + warp_row * 32 + i * 16 + (lane >> 2);
#pragma unroll
        for (int j = 0; j < 8; j++) {
            const int col = n0 + warp_col * 64 + j * 8 + 2 * (lane & 3);
#pragma unroll
            for (int r = 0; r < 2; r++) {
                const size_t off = (size_t)(row0 + r * 8) * DD + col;
                float2 v;
                v.x = acc[i][j][r * 2 + 0];
                v.y = acc[i][j][r * 2 + 1];
                *reinterpret_cast<float2*>(Cb + off) = v;
            }
        }
    }
}

// ---------------------------------------------------------------------------
// Elementwise tf32 rounding (vectorized)
// ---------------------------------------------------------------------------
__global__ void k_cvt(const float4* __restrict__ in, float4* __restrict__ out, int n4)
{
    int i = blockIdx.x * blockDim.x + threadIdx.x;
    if (i < n4) {
        float4 v = in[i];
        v.x = round_tf32(v.x); v.y = round_tf32(v.y);
        v.z = round_tf32(v.z); v.w = round_tf32(v.w);
        out[i] = v;
    }
}

// ---------------------------------------------------------------------------
// Tiled transpose with tf32 rounding: out[c][r] = tf32(in[r][c])
// ---------------------------------------------------------------------------
__global__ void k_transpose(const float* __restrict__ in, float* __restrict__ out,
                            int R, int C)
{
    __shared__ float tile[32][33];
    const int c0 = blockIdx.x * 32;
    const int r0 = blockIdx.y * 32;

#pragma unroll
    for (int i = threadIdx.y; i < 32; i += 8)
        tile[i][threadIdx.x] = in[(size_t)(r0 + i) * C + c0 + threadIdx.x];
    __syncthreads();
#pragma unroll
    for (int i = threadIdx.y; i < 32; i += 8)
        out[(size_t)(c0 + i) * R + r0 + threadIdx.x] = round_tf32(tile[threadIdx.x][i]);
}

// ---------------------------------------------------------------------------
// In-place row softmax on g_t2; output tf32-rounded.
// ---------------------------------------------------------------------------
__global__ void k_softmax()
{
    float* p = g_t2 + (size_t)blockIdx.x * QQ;
    const int tid = threadIdx.x;  // 256

    __shared__ float red[32];

    float m = -INFINITY;
    for (int i = tid; i < QQ; i += 256) m = fmaxf(m, p[i]);
#pragma unroll
    for (int o = 16; o > 0; o >>= 1) m = fmaxf(m, __shfl_xor_sync(0xffffffffu, m, o));
    if ((tid & 31) == 0) red[tid >> 5] = m;
    __syncthreads();
    if (tid < 32) {
        float v = (tid < 8) ? red[tid] : -INFINITY;
#pragma unroll
        for (int o = 4; o > 0; o >>= 1) v = fmaxf(v, __shfl_xor_sync(0xffffffffu, v, o));
        red[tid] = v;
    }
    __syncthreads();
    m = red[0];
    __syncthreads();

    float sum = 0.f;
    for (int i = tid; i < QQ; i += 256) {
        float e = __expf(p[i] - m);
        p[i] = e;
        sum += e;
    }
#pragma unroll
    for (int o = 16; o > 0; o >>= 1) sum += __shfl_xor_sync(0xffffffffu, sum, o);
    if ((tid & 31) == 0) red[tid >> 5] = sum;
    __syncthreads();
    if (tid < 32) {
        float v = (tid < 8) ? red[tid] : 0.f;
#pragma unroll
        for (int o = 4; o > 0; o >>= 1) v += __shfl_xor_sync(0xffffffffu, v, o);
        red[tid] = v;
    }
    __syncthreads();
    const float inv = 1.0f / red[0];

    for (int i = tid; i < QQ; i += 256) p[i] = round_tf32(p[i] * inv);
}

// ---------------------------------------------------------------------------
// Launcher
// ---------------------------------------------------------------------------
extern "C" void kernel_launch(void* const* d_in, const int* in_sizes, int n_in,
                              void* d_out, int out_size)
{
    const float* src  = (const float*)d_in[0];  // (B,S,D)
    const float* qry  = (const float*)d_in[1];  // (B,Q,D)
    const float* kern = (const float*)d_in[2];  // (Q,T)
    const float* wk   = (const float*)d_in[3];  // (D,Q)
    const float* wq   = (const float*)d_in[4];  // (S,D)
    float* out = (float*)d_out;                 // (B,Q,D)

    float *wkT, *kernT, *srcC, *qryC, *wqC;
    cudaGetSymbolAddress((void**)&wkT, g_wkT);
    cudaGetSymbolAddress((void**)&kernT, g_kernT);
    cudaGetSymbolAddress((void**)&srcC, g_srcC);
    cudaGetSymbolAddress((void**)&qryC, g_qryC);
    cudaGetSymbolAddress((void**)&wqC, g_wqC);

    // 0) operand prep (tf32 rounding + weight transposes)
    {
        int n4;
        n4 = (BB * SS * DD) / 4;
        k_cvt<<<(n4 + 255) / 256, 256>>>((const float4*)src, (float4*)srcC, n4);
        n4 = (BB * QQ * DD) / 4;
        k_cvt<<<(n4 + 255) / 256, 256>>>((const float4*)qry, (float4*)qryC, n4);
        n4 = (SS * DD) / 4;
        k_cvt<<<(n4 + 255) / 256, 256>>>((const float4*)wq, (float4*)wqC, n4);
    }
    const dim3 tb(32, 8);
    k_transpose<<<dim3(QQ / 32, DD / 32), tb>>>(wk, wkT, DD, QQ);
    k_transpose<<<dim3(QQ / 32, QQ / 32), tb>>>(kern, kernT, QQ, QQ);

    // 1) merged f_att: t1 = tanh(src@wk + wq@qry^T)   [ncu launch #6]
    gemm_fatt<<<dim3(QQ / BN, SS / BM, BB), 256>>>();

    // 2) sim: t2 = t1 @ kernT
    gemm_sim<<<dim3(QQ / BN, SS / BM, BB), 256>>>();

    // 3) softmax rows of t2
    k_softmax<<<BB * SS, 256>>>();

    // 4) out = sm^T @ src
    gemm_out<<<dim3(DD / BN, QQ / BM, BB), 256>>>(out);
}

// round 7
// speedup vs baseline: 7.6482x; 1.0600x over previous
#include <cuda_runtime.h>
#include <cstdint>
#include <math.h>

// Shapes (fixed)
#define BB 8
#define SS 2048
#define QQ 2048
#define DD 1024

// ---------------------------------------------------------------------------
// Scratch (device globals). "C" buffers hold tf32-rounded f32 bit patterns.
// ---------------------------------------------------------------------------
__device__ float g_t1[(size_t)BB * SS * QQ];          // tanh(f_att), tf32
__device__ float g_t2[(size_t)BB * SS * QQ];          // sim / softmax probs
__device__ float g_wkT[(size_t)QQ * DD];              // wkT[q][d], tf32
__device__ float g_kernT[(size_t)QQ * QQ];            // kernT[t][q], tf32
__device__ float g_srcC[(size_t)BB * SS * DD];        // src, tf32
__device__ float g_qryC[(size_t)BB * QQ * DD];        // query, tf32
__device__ float g_wqC[(size_t)SS * DD];              // wq, tf32

// ---------------------------------------------------------------------------
// PTX helpers (baseline PTX only — tcgen05 unavailable on compute_103 lowering)
// ---------------------------------------------------------------------------
__device__ __forceinline__ uint32_t f32_to_tf32(float x) {
    uint32_t r;
    asm("cvt.rna.tf32.f32 %0, %1;" : "=r"(r) : "f"(x));
    return r;
}
__device__ __forceinline__ float round_tf32(float x) {
    return __uint_as_float(f32_to_tf32(x));
}

__device__ __forceinline__ void mma_tf32(float* d, const uint32_t* a, const uint32_t* b) {
    asm volatile(
        "mma.sync.aligned.m16n8k8.row.col.f32.tf32.tf32.f32 "
        "{%0,%1,%2,%3}, {%4,%5,%6,%7}, {%8,%9}, {%0,%1,%2,%3};\n"
        : "+f"(d[0]), "+f"(d[1]), "+f"(d[2]), "+f"(d[3])
        : "r"(a[0]), "r"(a[1]), "r"(a[2]), "r"(a[3]), "r"(b[0]), "r"(b[1]));
}

__device__ __forceinline__ void ldsm_x4(uint32_t* r, uint32_t saddr) {
    asm volatile("ldmatrix.sync.aligned.m8n8.x4.shared.b16 {%0,%1,%2,%3}, [%4];"
                 : "=r"(r[0]), "=r"(r[1]), "=r"(r[2]), "=r"(r[3])
                 : "r"(saddr));
}

__device__ __forceinline__ void cp_async16(uint32_t smem_addr, const void* gptr) {
    asm volatile("cp.async.cg.shared.global [%0], [%1], 16;"
                 :: "r"(smem_addr), "l"(gptr));
}
#define CP_COMMIT() asm volatile("cp.async.commit_group;" ::: "memory")
#define CP_WAIT0()  asm volatile("cp.async.wait_group 0;" ::: "memory")

// ---------------------------------------------------------------------------
// Tile geometry: 128x128 CTA, BK=32, 256 threads (8 warps = 4(M) x 2(N)),
// warp tile 32x64. Double-buffered cp.async, one sync per K-tile.
// ---------------------------------------------------------------------------
#define BM 128
#define BN 128
#define BK 32
#define LDT 36                        // MK layout row stride (floats); 36%32=4 -> LDSM conflict-free
#define LDM 136                       // KM layout row stride
#define STAGE_F (BM * LDT)            // floats per operand stage
#define STAGE_BYTES (STAGE_F * 4)     // 18432 B
#define GSMEM_MK (4 * STAGE_BYTES)    // 73728 B: A[2] + B[2]

#define OUT_STAGE_BYTES (BK * LDM * 4)     // 17408 B
#define GSMEM_OUT (4 * OUT_STAGE_BYTES)    // 69632 B

// per-thread LDSM source byte offsets within one tile stage
struct LdsmOffs {
    uint32_t a[2];   // A fragments i=0,1
    uint32_t b[4];   // B fragment pairs jp=0..3
};

__device__ __forceinline__ LdsmOffs make_offs(int warp_row, int warp_col, int lane) {
    LdsmOffs o;
    const int sel = lane >> 3;
    const int rin = lane & 7;
#pragma unroll
    for (int i = 0; i < 2; i++) {
        int r = warp_row * 32 + i * 16 + (sel & 1) * 8 + rin;
        int c = (sel >> 1) * 4;
        o.a[i] = (uint32_t)((r * LDT + c) * 4);
    }
#pragma unroll
    for (int jp = 0; jp < 4; jp++) {
        int n = warp_col * 64 + jp * 16 + (sel >> 1) * 8 + rin;
        int c = (sel & 1) * 4;
        o.b[jp] = (uint32_t)((n * LDT + c) * 4);
    }
    return o;
}

// one k8 step: 6 LDSM.x4 + 16 MMA
__device__ __forceinline__ void mma_step(float acc[2][8][4],
                                         uint32_t aBase, uint32_t bBase,
                                         const LdsmOffs& o, int ks) {
    const uint32_t kadd = ks * 32;   // 8 floats
    uint32_t afr[2][4];
    ldsm_x4(afr[0], aBase + o.a[0] + kadd);
    ldsm_x4(afr[1], aBase + o.a[1] + kadd);
    uint32_t bfr[4][4];
#pragma unroll
    for (int jp = 0; jp < 4; jp++)
        ldsm_x4(bfr[jp], bBase + o.b[jp] + kadd);
#pragma unroll
    for (int i = 0; i < 2; i++)
#pragma unroll
        for (int j = 0; j < 8; j++)
            mma_tf32(acc[i][j], afr[i], &bfr[j >> 1][(j & 1) * 2]);
}

// ============================================================================
// Kernel A: merged f_att GEMM. K=2048 as two 1024 halves:
//   half 0: A=srcC[b], B=wkT ; half 1: A=wqC, B=qryC[b]
// Epilogue: tanh, tf32 store -> g_t1.
// ============================================================================
__global__ void __launch_bounds__(256, 2)
gemm_fatt()
{
    extern __shared__ uint32_t smem[];
    const uint32_t sBase = (uint32_t)__cvta_generic_to_shared(smem);
    const uint32_t asBase = sBase;                       // A stages [0,1]
    const uint32_t bsBase = sBase + 2 * STAGE_BYTES;     // B stages [0,1]

    const int tid = threadIdx.x;
    const int wid = tid >> 5;
    const int lane = tid & 31;
    const int warp_row = wid >> 1;
    const int warp_col = wid & 1;

    const int b  = blockIdx.z;
    const int m0 = blockIdx.y * BM;
    const int n0 = blockIdx.x * BN;

    const float* a_half[2] = { g_srcC + (size_t)b * SS * DD + (size_t)m0 * DD,
                               g_wqC  + (size_t)m0 * DD };
    const float* b_half[2] = { g_wkT  + (size_t)n0 * DD,
                               g_qryC + (size_t)b * QQ * DD + (size_t)n0 * DD };

    const int l_row = tid >> 3;          // 0..31
    const int l_c4  = (tid & 7) * 4;     // 0..28

    uint32_t wOff[4];
#pragma unroll
    for (int u = 0; u < 4; u++)
        wOff[u] = (uint32_t)(((l_row + 32 * u) * LDT + l_c4) * 4);

    const LdsmOffs offs = make_offs(warp_row, warp_col, lane);

    float acc[2][8][4];
#pragma unroll
    for (int i = 0; i < 2; i++)
#pragma unroll
        for (int j = 0; j < 8; j++)
#pragma unroll
            for (int r = 0; r < 4; r++) acc[i][j][r] = 0.f;

    const int ntiles = 2048 / BK;   // 64

    // prologue: tile 0
    {
        const float* ap = a_half[0] + (size_t)l_row * DD + l_c4;
        const float* bp = b_half[0] + (size_t)l_row * DD + l_c4;
#pragma unroll
        for (int u = 0; u < 4; u++) {
            cp_async16(asBase + wOff[u], ap + (size_t)(32 * u) * DD);
            cp_async16(bsBase + wOff[u], bp + (size_t)(32 * u) * DD);
        }
        CP_COMMIT();
    }

    for (int t = 0; t < ntiles; t++) {
        const uint32_t curOff = (uint32_t)(t & 1) * STAGE_BYTES;
        const uint32_t nxtOff = curOff ^ STAGE_BYTES;

        CP_WAIT0();
        __syncthreads();

        if (t + 1 < ntiles) {
            const int tt = t + 1;
            const int h  = tt >> 5;
            const int k0 = (tt & 31) * BK;
            const float* ap = a_half[h] + (size_t)l_row * DD + k0 + l_c4;
            const float* bp = b_half[h] + (size_t)l_row * DD + k0 + l_c4;
#pragma unroll
            for (int u = 0; u < 4; u++) {
                cp_async16(asBase + nxtOff + wOff[u], ap + (size_t)(32 * u) * DD);
                cp_async16(bsBase + nxtOff + wOff[u], bp + (size_t)(32 * u) * DD);
            }
            CP_COMMIT();
        }

#pragma unroll
        for (int ks = 0; ks < 4; ks++)
            mma_step(acc, asBase + curOff, bsBase + curOff, offs, ks);
    }

    float* Cb = g_t1 + (size_t)b * SS * QQ;
#pragma unroll
    for (int i = 0; i < 2; i++) {
        const int row0 = m0 + warp_row * 32 + i * 16 + (lane >> 2);
#pragma unroll
        for (int j = 0; j < 8; j++) {
            const int col = n0 + warp_col * 64 + j * 8 + 2 * (lane & 3);
#pragma unroll
            for (int r = 0; r < 2; r++) {
                const size_t off = (size_t)(row0 + r * 8) * QQ + col;
                float2 v;
                v.x = round_tf32(tanhf(acc[i][j][r * 2 + 0]));
                v.y = round_tf32(tanhf(acc[i][j][r * 2 + 1]));
                *reinterpret_cast<float2*>(Cb + off) = v;
            }
        }
    }
}

// ============================================================================
// Kernel B: sim GEMM. C[b][m][n] = sum_k t1[b][m][k] * kernT[n][k], K=2048.
// ============================================================================
__global__ void __launch_bounds__(256, 2)
gemm_sim()
{
    extern __shared__ uint32_t smem[];
    const uint32_t sBase = (uint32_t)__cvta_generic_to_shared(smem);
    const uint32_t asBase = sBase;
    const uint32_t bsBase = sBase + 2 * STAGE_BYTES;

    const int tid = threadIdx.x;
    const int wid = tid >> 5;
    const int lane = tid & 31;
    const int warp_row = wid >> 1;
    const int warp_col = wid & 1;

    const int b  = blockIdx.z;
    const int m0 = blockIdx.y * BM;
    const int n0 = blockIdx.x * BN;

    const float* Ab = g_t1 + (size_t)b * SS * QQ + (size_t)m0 * QQ;
    const float* Bb = g_kernT + (size_t)n0 * QQ;

    const int l_row = tid >> 3;
    const int l_c4  = (tid & 7) * 4;

    uint32_t wOff[4];
#pragma unroll
    for (int u = 0; u < 4; u++)
        wOff[u] = (uint32_t)(((l_row + 32 * u) * LDT + l_c4) * 4);

    const LdsmOffs offs = make_offs(warp_row, warp_col, lane);

    float acc[2][8][4];
#pragma unroll
    for (int i = 0; i < 2; i++)
#pragma unroll
        for (int j = 0; j < 8; j++)
#pragma unroll
            for (int r = 0; r < 4; r++) acc[i][j][r] = 0.f;

    const int ntiles = QQ / BK;   // 64

    {
        const float* ap = Ab + (size_t)l_row * QQ + l_c4;
        const float* bp = Bb + (size_t)l_row * QQ + l_c4;
#pragma unroll
        for (int u = 0; u < 4; u++) {
            cp_async16(asBase + wOff[u], ap + (size_t)(32 * u) * QQ);
            cp_async16(bsBase + wOff[u], bp + (size_t)(32 * u) * QQ);
        }
        CP_COMMIT();
    }

    for (int t = 0; t < ntiles; t++) {
        const uint32_t curOff = (uint32_t)(t & 1) * STAGE_BYTES;
        const uint32_t nxtOff = curOff ^ STAGE_BYTES;

        CP_WAIT0();
        __syncthreads();

        if (t + 1 < ntiles) {
            const int k0 = (t + 1) * BK;
            const float* ap = Ab + (size_t)l_row * QQ + k0 + l_c4;
            const float* bp = Bb + (size_t)l_row * QQ + k0 + l_c4;
#pragma unroll
            for (int u = 0; u < 4; u++) {
                cp_async16(asBase + nxtOff + wOff[u], ap + (size_t)(32 * u) * QQ);
                cp_async16(bsBase + nxtOff + wOff[u], bp + (size_t)(32 * u) * QQ);
            }
            CP_COMMIT();
        }

#pragma unroll
        for (int ks = 0; ks < 4; ks++)
            mma_step(acc, asBase + curOff, bsBase + curOff, offs, ks);
    }

    float* Cb = g_t2 + (size_t)b * SS * QQ;
#pragma unroll
    for (int i = 0; i < 2; i++) {
        const int row0 = m0 + warp_row * 32 + i * 16 + (lane >> 2);
#pragma unroll
        for (int j = 0; j < 8; j++) {
            const int col = n0 + warp_col * 64 + j * 8 + 2 * (lane & 3);
#pragma unroll
            for (int r = 0; r < 2; r++) {
                const size_t off = (size_t)(row0 + r * 8) * QQ + col;
                float2 v;
                v.x = acc[i][j][r * 2 + 0];
                v.y = acc[i][j][r * 2 + 1];
                *reinterpret_cast<float2*>(Cb + off) = v;
            }
        }
    }
}

// ============================================================================
// Kernel C: out[b][q][d] = sum_s sm[b][s][q] * src[b][s][d]  (KM layout, K=s)
// ============================================================================
__global__ void __launch_bounds__(256, 2)
gemm_out(float* __restrict__ C)
{
    extern __shared__ uint32_t smem[];
    const uint32_t sBase = (uint32_t)__cvta_generic_to_shared(smem);
    const uint32_t asBase = sBase;
    const uint32_t bsBase = sBase + 2 * OUT_STAGE_BYTES;

    const int tid = threadIdx.x;
    const int wid = tid >> 5;
    const int lane = tid & 31;
    const int warp_row = wid >> 1;
    const int warp_col = wid & 1;

    const int b  = blockIdx.z;
    const int m0 = blockIdx.y * BM;   // q
    const int n0 = blockIdx.x * BN;   // d

    const float* Ab = g_t2 + (size_t)b * SS * QQ + m0;
    const float* Bb = g_srcC + (size_t)b * SS * DD + n0;

    const int lr = tid >> 3;          // 0..31 (k rows)
    const int lc = (tid & 7) * 4;     // 0..28

    uint32_t w[4];
#pragma unroll
    for (int u = 0; u < 4; u++)
        w[u] = (uint32_t)((lr * LDM + lc + 32 * u) * 4);

    float acc[2][8][4];
#pragma unroll
    for (int i = 0; i < 2; i++)
#pragma unroll
        for (int j = 0; j < 8; j++)
#pragma unroll
            for (int r = 0; r < 4; r++) acc[i][j][r] = 0.f;

    const int ntiles = SS / BK;   // 64

    {
        const float* ap = Ab + (size_t)lr * QQ;
        const float* bp = Bb + (size_t)lr * DD;
#pragma unroll
        for (int u = 0; u < 4; u++) {
            cp_async16(asBase + w[u], ap + lc + 32 * u);
            cp_async16(bsBase + w[u], bp + lc + 32 * u);
        }
        CP_COMMIT();
    }

    const int a_row = warp_row * 32 + (lane >> 2);
    const int b_row = warp_col * 64 + (lane >> 2);
    const int kq    = lane & 3;

    uint32_t* AsG = smem;                               // generic views
    uint32_t* BsG = smem + 2 * (OUT_STAGE_BYTES / 4);

    for (int t = 0; t < ntiles; t++) {
        const int cur = t & 1;
        const uint32_t nxtOff = (uint32_t)(cur ^ 1) * OUT_STAGE_BYTES;
        const uint32_t* As = AsG + cur * (OUT_STAGE_BYTES / 4);
        const uint32_t* Bs = BsG + cur * (OUT_STAGE_BYTES / 4);

        CP_WAIT0();
        __syncthreads();

        if (t + 1 < ntiles) {
            const int k0 = (t + 1) * BK;
            const float* ap = Ab + (size_t)(k0 + lr) * QQ;
            const float* bp = Bb + (size_t)(k0 + lr) * DD;
#pragma unroll
            for (int u = 0; u < 4; u++) {
                cp_async16(asBase + nxtOff + w[u], ap + lc + 32 * u);
                cp_async16(bsBase + nxtOff + w[u], bp + lc + 32 * u);
            }
            CP_COMMIT();
        }

#pragma unroll
        for (int ks = 0; ks < 4; ks++) {
            const int kb = ks * 8 + kq;
            uint32_t afr[2][4];
#pragma unroll
            for (int i = 0; i < 2; i++) {
                const int r = a_row + i * 16;
                afr[i][0] = As[kb * LDM + r];
                afr[i][1] = As[kb * LDM + r + 8];
                afr[i][2] = As[(kb + 4) * LDM + r];
                afr[i][3] = As[(kb + 4) * LDM + r + 8];
            }
            uint32_t bfr[8][2];
#pragma unroll
            for (int j = 0; j < 8; j++) {
                const int r = b_row + j * 8;
                bfr[j][0] = Bs[kb * LDM + r];
                bfr[j][1] = Bs[(kb + 4) * LDM + r];
            }
#pragma unroll
            for (int i = 0; i < 2; i++)
#pragma unroll
                for (int j = 0; j < 8; j++)
                    mma_tf32(acc[i][j], afr[i], bfr[j]);
        }
    }

    float* Cb = C + (size_t)b * QQ * DD;
#pragma unroll
    for (int i = 0; i < 2; i++) {
        const int row0 = m0 + warp_row * 32 + i * 16 + (lane >> 2);
#pragma unroll
        for (int j = 0; j < 8; j++) {
            const int col = n0 + warp_col * 64 + j * 8 + 2 * (lane & 3);
#pragma unroll
            for (int r = 0; r < 2; r++) {
                const size_t off = (size_t)(row0 + r * 8) * DD + col;
                float2 v;
                v.x = acc[i][j][r * 2 + 0];
                v.y = acc[i][j][r * 2 + 1];
                *reinterpret_cast<float2*>(Cb + off) = v;
            }
        }
    }
}

// ---------------------------------------------------------------------------
// Elementwise tf32 rounding (vectorized)
// ---------------------------------------------------------------------------
__global__ void k_cvt(const float4* __restrict__ in, float4* __restrict__ out, int n4)
{
    int i = blockIdx.x * blockDim.x + threadIdx.x;
    if (i < n4) {
        float4 v = in[i];
        v.x = round_tf32(v.x); v.y = round_tf32(v.y);
        v.z = round_tf32(v.z); v.w = round_tf32(v.w);
        out[i] = v;
    }
}

// ---------------------------------------------------------------------------
// Tiled transpose with tf32 rounding: out[c][r] = tf32(in[r][c])
// ---------------------------------------------------------------------------
__global__ void k_transpose(const float* __restrict__ in, float* __restrict__ out,
                            int R, int C)
{
    __shared__ float tile[32][33];
    const int c0 = blockIdx.x * 32;
    const int r0 = blockIdx.y * 32;

#pragma unroll
    for (int i = threadIdx.y; i < 32; i += 8)
        tile[i][threadIdx.x] = in[(size_t)(r0 + i) * C + c0 + threadIdx.x];
    __syncthreads();
#pragma unroll
    for (int i = threadIdx.y; i < 32; i += 8)
        out[(size_t)(c0 + i) * R + r0 + threadIdx.x] = round_tf32(tile[threadIdx.x][i]);
}

// ---------------------------------------------------------------------------
// SMEM-resident row softmax on g_t2 (one 2048-float row per block; 1 read+1 write)
// Output tf32-rounded.
// ---------------------------------------------------------------------------
__global__ void __launch_bounds__(256)
k_softmax()
{
    __shared__ float4 rowv[QQ / 4];   // 8 KB
    __shared__ float red[32];

    float4* p = reinterpret_cast<float4*>(g_t2 + (size_t)blockIdx.x * QQ);
    const int tid = threadIdx.x;  // 256

    // load + max
    float m = -INFINITY;
#pragma unroll
    for (int i = tid; i < QQ / 4; i += 256) {
        float4 v = p[i];
        rowv[i] = v;
        m = fmaxf(m, fmaxf(fmaxf(v.x, v.y), fmaxf(v.z, v.w)));
    }
#pragma unroll
    for (int o = 16; o > 0; o >>= 1) m = fmaxf(m, __shfl_xor_sync(0xffffffffu, m, o));
    if ((tid & 31) == 0) red[tid >> 5] = m;
    __syncthreads();
    if (tid < 32) {
        float v = (tid < 8) ? red[tid] : -INFINITY;
#pragma unroll
        for (int o = 4; o > 0; o >>= 1) v = fmaxf(v, __shfl_xor_sync(0xffffffffu, v, o));
        red[tid] = v;
    }
    __syncthreads();
    m = red[0];
    __syncthreads();

    // exp + sum (in smem)
    float sum = 0.f;
#pragma unroll
    for (int i = tid; i < QQ / 4; i += 256) {
        float4 v = rowv[i];
        v.x = __expf(v.x - m); v.y = __expf(v.y - m);
        v.z = __expf(v.z - m); v.w = __expf(v.w - m);
        rowv[i] = v;
        sum += v.x + v.y + v.z + v.w;
    }
#pragma unroll
    for (int o = 16; o > 0; o >>= 1) sum += __shfl_xor_sync(0xffffffffu, sum, o);
    if ((tid & 31) == 0) red[tid >> 5] = sum;
    __syncthreads();
    if (tid < 32) {
        float v = (tid < 8) ? red[tid] : 0.f;
#pragma unroll
        for (int o = 4; o > 0; o >>= 1) v += __shfl_xor_sync(0xffffffffu, v, o);
        red[tid] = v;
    }
    __syncthreads();
    const float inv = 1.0f / red[0];

    // normalize + tf32 round + store
#pragma unroll
    for (int i = tid; i < QQ / 4; i += 256) {
        float4 v = rowv[i];
        v.x = round_tf32(v.x * inv); v.y = round_tf32(v.y * inv);
        v.z = round_tf32(v.z * inv); v.w = round_tf32(v.w * inv);
        p[i] = v;
    }
}

// ---------------------------------------------------------------------------
// Launcher
// ---------------------------------------------------------------------------
extern "C" void kernel_launch(void* const* d_in, const int* in_sizes, int n_in,
                              void* d_out, int out_size)
{
    const float* src  = (const float*)d_in[0];  // (B,S,D)
    const float* qry  = (const float*)d_in[1];  // (B,Q,D)
    const float* kern = (const float*)d_in[2];  // (Q,T)
    const float* wk   = (const float*)d_in[3];  // (D,Q)
    const float* wq   = (const float*)d_in[4];  // (S,D)
    float* out = (float*)d_out;                 // (B,Q,D)

    float *srcC, *qryC, *wqC, *wkT, *kernT;
    cudaGetSymbolAddress((void**)&srcC, g_srcC);
    cudaGetSymbolAddress((void**)&qryC, g_qryC);
    cudaGetSymbolAddress((void**)&wqC, g_wqC);
    cudaGetSymbolAddress((void**)&wkT, g_wkT);
    cudaGetSymbolAddress((void**)&kernT, g_kernT);

    cudaFuncSetAttribute(gemm_fatt, cudaFuncAttributeMaxDynamicSharedMemorySize, GSMEM_MK);
    cudaFuncSetAttribute(gemm_sim,  cudaFuncAttributeMaxDynamicSharedMemorySize, GSMEM_MK);
    cudaFuncSetAttribute(gemm_out,  cudaFuncAttributeMaxDynamicSharedMemorySize, GSMEM_OUT);

    // 0) operand prep (tf32 rounding + weight transposes)
    {
        int n4;
        n4 = (BB * SS * DD) / 4;
        k_cvt<<<(n4 + 255) / 256, 256>>>((const float4*)src, (float4*)srcC, n4);
        n4 = (BB * QQ * DD) / 4;
        k_cvt<<<(n4 + 255) / 256, 256>>>((const float4*)qry, (float4*)qryC, n4);
        n4 = (SS * DD) / 4;
        k_cvt<<<(n4 + 255) / 256, 256>>>((const float4*)wq, (float4*)wqC, n4);
    }
    const dim3 tb(32, 8);
    k_transpose<<<dim3(QQ / 32, DD / 32), tb>>>(wk, wkT, DD, QQ);
    k_transpose<<<dim3(QQ / 32, QQ / 32), tb>>>(kern, kernT, QQ, QQ);

    // 1) merged f_att: t1 = tanh(src@wk + wq@qry^T)
    gemm_fatt<<<dim3(QQ / BN, SS / BM, BB), 256, GSMEM_MK>>>();

    // 2) sim: t2 = t1 @ kernT
    gemm_sim<<<dim3(QQ / BN, SS / BM, BB), 256, GSMEM_MK>>>();

    // 3) softmax rows of t2
    k_softmax<<<BB * SS, 256>>>();

    // 4) out = sm^T @ src
    gemm_out<<<dim3(DD / BN, QQ / BM, BB), 256, GSMEM_OUT>>>(out);
}

// round 9
// speedup vs baseline: 13.3861x; 1.7502x over previous
#include <cuda_runtime.h>
#include <cuda_fp16.h>
#include <cstdint>
#include <math.h>

// Shapes (fixed)
#define BB 8
#define SS 2048
#define QQ 2048
#define DD 1024

// ---------------------------------------------------------------------------
// Scratch (device globals). fp16 operands, f32 where accumulation precision matters.
// ---------------------------------------------------------------------------
__device__ __half g_t1h[(size_t)BB * SS * QQ];        // tanh(f_att) fp16
__device__ float  g_t2[(size_t)BB * SS * QQ];         // sim (f32 for softmax)
__device__ __half g_ph[(size_t)BB * SS * QQ];         // softmax probs fp16
__device__ __half g_wkTh[(size_t)QQ * DD];            // wkT[q][d]
__device__ __half g_kernTh[(size_t)QQ * QQ];          // kernT[t][q]
__device__ __half g_srch[(size_t)BB * SS * DD];       // src fp16
__device__ __half g_qryh[(size_t)BB * QQ * DD];       // query fp16
__device__ __half g_wqh[(size_t)SS * DD];             // wq fp16

// ---------------------------------------------------------------------------
// PTX helpers (baseline PTX)
// ---------------------------------------------------------------------------
__device__ __forceinline__ uint32_t h2_as_u32(__half2 h) {
    uint32_t u;
    __builtin_memcpy(&u, &h, sizeof(u));
    return u;
}

__device__ __forceinline__ void mma_f16(float* d, const uint32_t* a, const uint32_t* b) {
    asm volatile(
        "mma.sync.aligned.m16n8k16.row.col.f32.f16.f16.f32 "
        "{%0,%1,%2,%3}, {%4,%5,%6,%7}, {%8,%9}, {%0,%1,%2,%3};\n"
        : "+f"(d[0]), "+f"(d[1]), "+f"(d[2]), "+f"(d[3])
        : "r"(a[0]), "r"(a[1]), "r"(a[2]), "r"(a[3]), "r"(b[0]), "r"(b[1]));
}

__device__ __forceinline__ void ldsm_x4(uint32_t* r, uint32_t saddr) {
    asm volatile("ldmatrix.sync.aligned.m8n8.x4.shared.b16 {%0,%1,%2,%3}, [%4];"
                 : "=r"(r[0]), "=r"(r[1]), "=r"(r[2]), "=r"(r[3])
                 : "r"(saddr));
}
__device__ __forceinline__ void ldsm_x4_t(uint32_t* r, uint32_t saddr) {
    asm volatile("ldmatrix.sync.aligned.m8n8.x4.trans.shared.b16 {%0,%1,%2,%3}, [%4];"
                 : "=r"(r[0]), "=r"(r[1]), "=r"(r[2]), "=r"(r[3])
                 : "r"(saddr));
}

__device__ __forceinline__ void cp_async16(uint32_t smem_addr, const void* gptr) {
    asm volatile("cp.async.cg.shared.global [%0], [%1], 16;"
                 :: "r"(smem_addr), "l"(gptr));
}
#define CP_COMMIT() asm volatile("cp.async.commit_group;" ::: "memory")
#define CP_WAIT1()  asm volatile("cp.async.wait_group 1;" ::: "memory")

// ---------------------------------------------------------------------------
// Geometry: 128x128 CTA tile, BK=32 (halves), 256 threads (8 warps = 4Mx2N),
// warp tile 32x64, 2x8 m16n8 fragments. 3-stage cp.async pipeline.
// ---------------------------------------------------------------------------
#define BM 128
#define BN 128
#define BK 32
#define LDTH 40                             // MK row stride (halves): 80B -> LDSM conflict-free
#define LDMH 136                            // KM row stride (halves): 272B -> conflict-free
#define STG_MK (BM * LDTH * 2)              // 10240 B / operand / stage
#define GSMEM_MK (6 * STG_MK)               // 61440 B
#define STG_KM (BK * LDMH * 2)              // 8704 B
#define GSMEM_KM (6 * STG_KM)               // 52224 B

// per-thread LDSM source byte offsets within one MK stage
struct LdsmOffs { uint32_t a[2]; uint32_t b[4]; };

__device__ __forceinline__ LdsmOffs make_offs_mk(int warp_row, int warp_col, int lane) {
    LdsmOffs o;
    const int sel = lane >> 3, rin = lane & 7;
#pragma unroll
    for (int i = 0; i < 2; i++) {
        int r = warp_row * 32 + i * 16 + (sel & 1) * 8 + rin;   // m row
        int c = (sel >> 1) * 8;                                 // k halves
        o.a[i] = (uint32_t)((r * LDTH + c) * 2);
    }
#pragma unroll
    for (int jp = 0; jp < 4; jp++) {
        int n = warp_col * 64 + jp * 16 + (sel >> 1) * 8 + rin; // n row
        int c = (sel & 1) * 8;                                  // k halves
        o.b[jp] = (uint32_t)((n * LDTH + c) * 2);
    }
    return o;
}

// one k16 step (MK): 6 LDSM.x4 + 16 MMA
__device__ __forceinline__ void mma_step_mk(float acc[2][8][4],
                                            uint32_t aBase, uint32_t bBase,
                                            const LdsmOffs& o, int ks) {
    const uint32_t kadd = ks * 32;   // 16 halves
    uint32_t afr[2][4];
    ldsm_x4(afr[0], aBase + o.a[0] + kadd);
    ldsm_x4(afr[1], aBase + o.a[1] + kadd);
    uint32_t bfr[4][4];
#pragma unroll
    for (int jp = 0; jp < 4; jp++)
        ldsm_x4(bfr[jp], bBase + o.b[jp] + kadd);
#pragma unroll
    for (int i = 0; i < 2; i++)
#pragma unroll
        for (int j = 0; j < 8; j++)
            mma_f16(acc[i][j], afr[i], &bfr[j >> 1][(j & 1) * 2]);
}

// ============================================================================
// Kernel A: merged f_att GEMM (MK layout). K=2048 as two 1024 halves:
//   half 0: A=srch[b], B=wkTh ; half 1: A=wqh, B=qryh[b]
// Epilogue: tanh -> fp16 g_t1h.
// ============================================================================
__global__ void __launch_bounds__(256, 2)
gemm_fatt()
{
    extern __shared__ uint32_t smem[];
    const uint32_t sBase = (uint32_t)__cvta_generic_to_shared(smem);
    const uint32_t asBase = sBase;
    const uint32_t bsBase = sBase + 3 * STG_MK;

    const int tid = threadIdx.x;
    const int wid = tid >> 5;
    const int lane = tid & 31;
    const int warp_row = wid >> 1;
    const int warp_col = wid & 1;

    const int b  = blockIdx.z;
    const int m0 = blockIdx.y * BM;
    const int n0 = blockIdx.x * BN;

    const __half* a_half[2] = { g_srch + (size_t)b * SS * DD + (size_t)m0 * DD,
                                g_wqh  + (size_t)m0 * DD };
    const __half* b_half[2] = { g_wkTh + (size_t)n0 * DD,
                                g_qryh + (size_t)b * QQ * DD + (size_t)n0 * DD };

    const int l_row = tid >> 2;          // 0..63
    const int l_c8  = (tid & 3) * 8;     // halves 0,8,16,24

    uint32_t wOff[2];
#pragma unroll
    for (int u = 0; u < 2; u++)
        wOff[u] = (uint32_t)(((l_row + 64 * u) * LDTH + l_c8) * 2);

    const LdsmOffs offs = make_offs_mk(warp_row, warp_col, lane);

    float acc[2][8][4];
#pragma unroll
    for (int i = 0; i < 2; i++)
#pragma unroll
        for (int j = 0; j < 8; j++)
#pragma unroll
            for (int r = 0; r < 4; r++) acc[i][j][r] = 0.f;

    const int ntiles = 2048 / BK;   // 64

    // prologue: stages 0,1 (both in half 0 since 2 < 32)
#pragma unroll
    for (int p = 0; p < 2; p++) {
        const int k0 = p * BK;
        const __half* ap = a_half[0] + (size_t)l_row * DD + k0 + l_c8;
        const __half* bp = b_half[0] + (size_t)l_row * DD + k0 + l_c8;
        const uint32_t so = p * STG_MK;
#pragma unroll
        for (int u = 0; u < 2; u++) {
            cp_async16(asBase + so + wOff[u], ap + (size_t)(64 * u) * DD);
            cp_async16(bsBase + so + wOff[u], bp + (size_t)(64 * u) * DD);
        }
        CP_COMMIT();
    }

    for (int t = 0; t < ntiles; t++) {
        CP_WAIT1();
        __syncthreads();

        if (t + 2 < ntiles) {
            const int tt = t + 2;
            const int h  = tt >> 5;
            const int k0 = (tt & 31) * BK;
            const uint32_t so = (uint32_t)(tt % 3) * STG_MK;
            const __half* ap = a_half[h] + (size_t)l_row * DD + k0 + l_c8;
            const __half* bp = b_half[h] + (size_t)l_row * DD + k0 + l_c8;
#pragma unroll
            for (int u = 0; u < 2; u++) {
                cp_async16(asBase + so + wOff[u], ap + (size_t)(64 * u) * DD);
                cp_async16(bsBase + so + wOff[u], bp + (size_t)(64 * u) * DD);
            }
            CP_COMMIT();
        }

        const uint32_t co = (uint32_t)(t % 3) * STG_MK;
        mma_step_mk(acc, asBase + co, bsBase + co, offs, 0);
        mma_step_mk(acc, asBase + co, bsBase + co, offs, 1);
    }

    __half* Cb = g_t1h + (size_t)b * SS * QQ;
#pragma unroll
    for (int i = 0; i < 2; i++) {
        const int row0 = m0 + warp_row * 32 + i * 16 + (lane >> 2);
#pragma unroll
        for (int j = 0; j < 8; j++) {
            const int col = n0 + warp_col * 64 + j * 8 + 2 * (lane & 3);
#pragma unroll
            for (int r = 0; r < 2; r++) {
                const size_t off = (size_t)(row0 + r * 8) * QQ + col;
                __half2 h = __floats2half2_rn(tanhf(acc[i][j][r * 2 + 0]),
                                              tanhf(acc[i][j][r * 2 + 1]));
                *reinterpret_cast<__half2*>(Cb + off) = h;
            }
        }
    }
}

// ============================================================================
// Kernel B: sim GEMM (MK). C[b][m][n] = sum_k t1h[b][m][k] * kernTh[n][k], K=2048.
// Epilogue: f32 -> g_t2.
// ============================================================================
__global__ void __launch_bounds__(256, 2)
gemm_sim()
{
    extern __shared__ uint32_t smem[];
    const uint32_t sBase = (uint32_t)__cvta_generic_to_shared(smem);
    const uint32_t asBase = sBase;
    const uint32_t bsBase = sBase + 3 * STG_MK;

    const int tid = threadIdx.x;
    const int wid = tid >> 5;
    const int lane = tid & 31;
    const int warp_row = wid >> 1;
    const int warp_col = wid & 1;

    const int b  = blockIdx.z;
    const int m0 = blockIdx.y * BM;
    const int n0 = blockIdx.x * BN;

    const __half* Ab = g_t1h + (size_t)b * SS * QQ + (size_t)m0 * QQ;
    const __half* Bb = g_kernTh + (size_t)n0 * QQ;

    const int l_row = tid >> 2;
    const int l_c8  = (tid & 3) * 8;

    uint32_t wOff[2];
#pragma unroll
    for (int u = 0; u < 2; u++)
        wOff[u] = (uint32_t)(((l_row + 64 * u) * LDTH + l_c8) * 2);

    const LdsmOffs offs = make_offs_mk(warp_row, warp_col, lane);

    float acc[2][8][4];
#pragma unroll
    for (int i = 0; i < 2; i++)
#pragma unroll
        for (int j = 0; j < 8; j++)
#pragma unroll
            for (int r = 0; r < 4; r++) acc[i][j][r] = 0.f;

    const int ntiles = QQ / BK;   // 64

#pragma unroll
    for (int p = 0; p < 2; p++) {
        const int k0 = p * BK;
        const __half* ap = Ab + (size_t)l_row * QQ + k0 + l_c8;
        const __half* bp = Bb + (size_t)l_row * QQ + k0 + l_c8;
        const uint32_t so = p * STG_MK;
#pragma unroll
        for (int u = 0; u < 2; u++) {
            cp_async16(asBase + so + wOff[u], ap + (size_t)(64 * u) * QQ);
            cp_async16(bsBase + so + wOff[u], bp + (size_t)(64 * u) * QQ);
        }
        CP_COMMIT();
    }

    for (int t = 0; t < ntiles; t++) {
        CP_WAIT1();
        __syncthreads();

        if (t + 2 < ntiles) {
            const int k0 = (t + 2) * BK;
            const uint32_t so = (uint32_t)((t + 2) % 3) * STG_MK;
            const __half* ap = Ab + (size_t)l_row * QQ + k0 + l_c8;
            const __half* bp = Bb + (size_t)l_row * QQ + k0 + l_c8;
#pragma unroll
            for (int u = 0; u < 2; u++) {
                cp_async16(asBase + so + wOff[u], ap + (size_t)(64 * u) * QQ);
                cp_async16(bsBase + so + wOff[u], bp + (size_t)(64 * u) * QQ);
            }
            CP_COMMIT();
        }

        const uint32_t co = (uint32_t)(t % 3) * STG_MK;
        mma_step_mk(acc, asBase + co, bsBase + co, offs, 0);
        mma_step_mk(acc, asBase + co, bsBase + co, offs, 1);
    }

    float* Cb = g_t2 + (size_t)b * SS * QQ;
#pragma unroll
    for (int i = 0; i < 2; i++) {
        const int row0 = m0 + warp_row * 32 + i * 16 + (lane >> 2);
#pragma unroll
        for (int j = 0; j < 8; j++) {
            const int col = n0 + warp_col * 64 + j * 8 + 2 * (lane & 3);
#pragma unroll
            for (int r = 0; r < 2; r++) {
                const size_t off = (size_t)(row0 + r * 8) * QQ + col;
                float2 v;
                v.x = acc[i][j][r * 2 + 0];
                v.y = acc[i][j][r * 2 + 1];
                *reinterpret_cast<float2*>(Cb + off) = v;
            }
        }
    }
}

// ============================================================================
// Kernel C: out[b][q][d] = sum_s ph[b][s][q] * srch[b][s][d]  (KM layout, K=s)
// Uses ldmatrix.trans (b16) for both operands.
// ============================================================================
__global__ void __launch_bounds__(256, 2)
gemm_out(float* __restrict__ C)
{
    extern __shared__ uint32_t smem[];
    const uint32_t sBase = (uint32_t)__cvta_generic_to_shared(smem);
    const uint32_t asBase = sBase;
    const uint32_t bsBase = sBase + 3 * STG_KM;

    const int tid = threadIdx.x;
    const int wid = tid >> 5;
    const int lane = tid & 31;
    const int warp_row = wid >> 1;
    const int warp_col = wid & 1;

    const int b  = blockIdx.z;
    const int m0 = blockIdx.y * BM;   // q
    const int n0 = blockIdx.x * BN;   // d

    const __half* Ab = g_ph + (size_t)b * SS * QQ + m0;
    const __half* Bb = g_srch + (size_t)b * SS * DD + n0;

    const int lk = tid >> 3;          // 0..31 (k rows)
    const int lc = (tid & 7) * 8;     // halves 0..56

    uint32_t w[2];
#pragma unroll
    for (int u = 0; u < 2; u++)
        w[u] = (uint32_t)((lk * LDMH + lc + 64 * u) * 2);

    // trans LDSM offsets
    const int sel = lane >> 3, rin = lane & 7;
    uint32_t oa[2], ob[4];
#pragma unroll
    for (int i = 0; i < 2; i++)
        oa[i] = (uint32_t)((((sel >> 1) * 8 + rin) * LDMH
                           + warp_row * 32 + i * 16 + (sel & 1) * 8) * 2);
#pragma unroll
    for (int jp = 0; jp < 4; jp++)
        ob[jp] = (uint32_t)((((sel & 1) * 8 + rin) * LDMH
                           + warp_col * 64 + jp * 16 + (sel >> 1) * 8) * 2);

    float acc[2][8][4];
#pragma unroll
    for (int i = 0; i < 2; i++)
#pragma unroll
        for (int j = 0; j < 8; j++)
#pragma unroll
            for (int r = 0; r < 4; r++) acc[i][j][r] = 0.f;

    const int ntiles = SS / BK;   // 64

#pragma unroll
    for (int p = 0; p < 2; p++) {
        const __half* ap = Ab + (size_t)(p * BK + lk) * QQ;
        const __half* bp = Bb + (size_t)(p * BK + lk) * DD;
        const uint32_t so = p * STG_KM;
#pragma unroll
        for (int u = 0; u < 2; u++) {
            cp_async16(asBase + so + w[u], ap + lc + 64 * u);
            cp_async16(bsBase + so + w[u], bp + lc + 64 * u);
        }
        CP_COMMIT();
    }

    for (int t = 0; t < ntiles; t++) {
        CP_WAIT1();
        __syncthreads();

        if (t + 2 < ntiles) {
            const int k0 = (t + 2) * BK;
            const uint32_t so = (uint32_t)((t + 2) % 3) * STG_KM;
            const __half* ap = Ab + (size_t)(k0 + lk) * QQ;
            const __half* bp = Bb + (size_t)(k0 + lk) * DD;
#pragma unroll
            for (int u = 0; u < 2; u++) {
                cp_async16(asBase + so + w[u], ap + lc + 64 * u);
                cp_async16(bsBase + so + w[u], bp + lc + 64 * u);
            }
            CP_COMMIT();
        }

        const uint32_t aB = asBase + (uint32_t)(t % 3) * STG_KM;
        const uint32_t bB = bsBase + (uint32_t)(t % 3) * STG_KM;

#pragma unroll
        for (int ks = 0; ks < 2; ks++) {
            const uint32_t kadd = (uint32_t)(ks * 16 * LDMH * 2);
            uint32_t afr[2][4];
            ldsm_x4_t(afr[0], aB + oa[0] + kadd);
            ldsm_x4_t(afr[1], aB + oa[1] + kadd);
            uint32_t bfr[4][4];
#pragma unroll
            for (int jp = 0; jp < 4; jp++)
                ldsm_x4_t(bfr[jp], bB + ob[jp] + kadd);
#pragma unroll
            for (int i = 0; i < 2; i++)
#pragma unroll
                for (int j = 0; j < 8; j++)
                    mma_f16(acc[i][j], afr[i], &bfr[j >> 1][(j & 1) * 2]);
        }
    }

    float* Cb = C + (size_t)b * QQ * DD;
#pragma unroll
    for (int i = 0; i < 2; i++) {
        const int row0 = m0 + warp_row * 32 + i * 16 + (lane >> 2);
#pragma unroll
        for (int j = 0; j < 8; j++) {
            const int col = n0 + warp_col * 64 + j * 8 + 2 * (lane & 3);
#pragma unroll
            for (int r = 0; r < 2; r++) {
                const size_t off = (size_t)(row0 + r * 8) * DD + col;
                float2 v;
                v.x = acc[i][j][r * 2 + 0];
                v.y = acc[i][j][r * 2 + 1];
                *reinterpret_cast<float2*>(Cb + off) = v;
            }
        }
    }
}

// ---------------------------------------------------------------------------
// Elementwise f32 -> fp16 (vectorized: 1 float4 -> 4 halves)
// ---------------------------------------------------------------------------
__global__ void k_cvt_h(const float4* __restrict__ in, uint2* __restrict__ out, int n4)
{
    int i = blockIdx.x * blockDim.x + threadIdx.x;
    if (i < n4) {
        float4 v = in[i];
        uint2 o;
        o.x = h2_as_u32(__floats2half2_rn(v.x, v.y));
        o.y = h2_as_u32(__floats2half2_rn(v.z, v.w));
        out[i] = o;
    }
}

// ---------------------------------------------------------------------------
// Tiled transpose f32 -> fp16: out[c][r] = h(in[r][c])
// ---------------------------------------------------------------------------
__global__ void k_transpose_h(const float* __restrict__ in, __half* __restrict__ out,
                              int R, int C)
{
    __shared__ float tile[32][33];
    const int c0 = blockIdx.x * 32;
    const int r0 = blockIdx.y * 32;

#pragma unroll
    for (int i = threadIdx.y; i < 32; i += 8)
        tile[i][threadIdx.x] = in[(size_t)(r0 + i) * C + c0 + threadIdx.x];
    __syncthreads();
#pragma unroll
    for (int i = threadIdx.y; i < 32; i += 8)
        out[(size_t)(c0 + i) * R + r0 + threadIdx.x] = __float2half_rn(tile[threadIdx.x][i]);
}

// ---------------------------------------------------------------------------
// SMEM-resident row softmax: read f32 g_t2, write fp16 g_ph.
// ---------------------------------------------------------------------------
__global__ void __launch_bounds__(256)
k_softmax()
{
    __shared__ float4 rowv[QQ / 4];   // 8 KB
    __shared__ float red[32];

    const float4* p = reinterpret_cast<const float4*>(g_t2 + (size_t)blockIdx.x * QQ);
    __half2* q = reinterpret_cast<__half2*>(g_ph + (size_t)blockIdx.x * QQ);
    const int tid = threadIdx.x;  // 256

    float m = -INFINITY;
#pragma unroll
    for (int i = tid; i < QQ / 4; i += 256) {
        float4 v = p[i];
        rowv[i] = v;
        m = fmaxf(m, fmaxf(fmaxf(v.x, v.y), fmaxf(v.z, v.w)));
    }
#pragma unroll
    for (int o = 16; o > 0; o >>= 1) m = fmaxf(m, __shfl_xor_sync(0xffffffffu, m, o));
    if ((tid & 31) == 0) red[tid >> 5] = m;
    __syncthreads();
    if (tid < 32) {
        float v = (tid < 8) ? red[tid] : -INFINITY;
#pragma unroll
        for (int o = 4; o > 0; o >>= 1) v = fmaxf(v, __shfl_xor_sync(0xffffffffu, v, o));
        red[tid] = v;
    }
    __syncthreads();
    m = red[0];
    __syncthreads();

    float sum = 0.f;
#pragma unroll
    for (int i = tid; i < QQ / 4; i += 256) {
        float4 v = rowv[i];
        v.x = __expf(v.x - m); v.y = __expf(v.y - m);
        v.z = __expf(v.z - m); v.w = __expf(v.w - m);
        rowv[i] = v;
        sum += v.x + v.y + v.z + v.w;
    }
#pragma unroll
    for (int o = 16; o > 0; o >>= 1) sum += __shfl_xor_sync(0xffffffffu, sum, o);
    if ((tid & 31) == 0) red[tid >> 5] = sum;
    __syncthreads();
    if (tid < 32) {
        float v = (tid < 8) ? red[tid] : 0.f;
#pragma unroll
        for (int o = 4; o > 0; o >>= 1) v += __shfl_xor_sync(0xffffffffu, v, o);
        red[tid] = v;
    }
    __syncthreads();
    const float inv = 1.0f / red[0];

#pragma unroll
    for (int i = tid; i < QQ / 4; i += 256) {
        float4 v = rowv[i];
        q[2 * i + 0] = __floats2half2_rn(v.x * inv, v.y * inv);
        q[2 * i + 1] = __floats2half2_rn(v.z * inv, v.w * inv);
    }
}

// ---------------------------------------------------------------------------
// Launcher
// ---------------------------------------------------------------------------
extern "C" void kernel_launch(void* const* d_in, const int* in_sizes, int n_in,
                              void* d_out, int out_size)
{
    const float* src  = (const float*)d_in[0];  // (B,S,D)
    const float* qry  = (const float*)d_in[1];  // (B,Q,D)
    const float* kern = (const float*)d_in[2];  // (Q,T)
    const float* wk   = (const float*)d_in[3];  // (D,Q)
    const float* wq   = (const float*)d_in[4];  // (S,D)
    float* out = (float*)d_out;                 // (B,Q,D)

    __half *srch, *qryh, *wqh, *wkTh, *kernTh;
    cudaGetSymbolAddress((void**)&srch, g_srch);
    cudaGetSymbolAddress((void**)&qryh, g_qryh);
    cudaGetSymbolAddress((void**)&wqh, g_wqh);
    cudaGetSymbolAddress((void**)&wkTh, g_wkTh);
    cudaGetSymbolAddress((void**)&kernTh, g_kernTh);

    cudaFuncSetAttribute(gemm_fatt, cudaFuncAttributeMaxDynamicSharedMemorySize, GSMEM_MK);
    cudaFuncSetAttribute(gemm_sim,  cudaFuncAttributeMaxDynamicSharedMemorySize, GSMEM_MK);
    cudaFuncSetAttribute(gemm_out,  cudaFuncAttributeMaxDynamicSharedMemorySize, GSMEM_KM);

    // 0) operand prep: fp16 conversions + fp16 weight transposes
    {
        int n4;
        n4 = (BB * SS * DD) / 4;
        k_cvt_h<<<(n4 + 255) / 256, 256>>>((const float4*)src, (uint2*)srch, n4);
        n4 = (BB * QQ * DD) / 4;
        k_cvt_h<<<(n4 + 255) / 256, 256>>>((const float4*)qry, (uint2*)qryh, n4);
        n4 = (SS * DD) / 4;
        k_cvt_h<<<(n4 + 255) / 256, 256>>>((const float4*)wq, (uint2*)wqh, n4);
    }
    const dim3 tb(32, 8);
    k_transpose_h<<<dim3(QQ / 32, DD / 32), tb>>>(wk, wkTh, DD, QQ);
    k_transpose_h<<<dim3(QQ / 32, QQ / 32), tb>>>(kern, kernTh, QQ, QQ);

    // 1) merged f_att: t1h = tanh(src@wk + wq@qry^T)
    gemm_fatt<<<dim3(QQ / BN, SS / BM, BB), 256, GSMEM_MK>>>();

    // 2) sim: t2 = t1h @ kernTh  (f32 out)
    gemm_sim<<<dim3(QQ / BN, SS / BM, BB), 256, GSMEM_MK>>>();

    // 3) softmax rows -> fp16 probs
    k_softmax<<<BB * SS, 256>>>();

    // 4) out = probs^T @ src
    gemm_out<<<dim3(DD / BN, QQ / BM, BB), 256, GSMEM_KM>>>(out);
}

// round 10
// speedup vs baseline: 13.5155x; 1.0097x over previous
#include <cuda_runtime.h>
#include <cuda_fp16.h>
#include <cstdint>
#include <math.h>

// Shapes (fixed)
#define BB 8
#define SS 2048
#define QQ 2048
#define DD 1024

// ---------------------------------------------------------------------------
// Scratch (device globals). fp16 operands, f32 where accumulation precision matters.
// ---------------------------------------------------------------------------
__device__ __half g_t1h[(size_t)BB * SS * QQ];        // tanh(f_att) fp16
__device__ float  g_t2[(size_t)BB * SS * QQ];         // sim (f32 for softmax)
__device__ __half g_ph[(size_t)BB * SS * QQ];         // softmax probs fp16
__device__ __half g_wkTh[(size_t)QQ * DD];            // wkT[q][d]
__device__ __half g_kernTh[(size_t)QQ * QQ];          // kernT[t][q]
__device__ __half g_srch[(size_t)BB * SS * DD];       // src fp16
__device__ __half g_qryh[(size_t)BB * QQ * DD];       // query fp16
__device__ __half g_wqh[(size_t)SS * DD];             // wq fp16

// ---------------------------------------------------------------------------
// PTX helpers (baseline PTX)
// ---------------------------------------------------------------------------
__device__ __forceinline__ uint32_t h2_as_u32(__half2 h) {
    uint32_t u;
    __builtin_memcpy(&u, &h, sizeof(u));
    return u;
}

// fast accurate tanh: 1 - 2/(e^{2x}+1). __expf err ~2ulp -> tanh err ~1e-6.
// x->+inf: e->inf -> 1 ; x->-inf: e->0 -> -1. Safe for all finite f_att.
__device__ __forceinline__ float fast_tanh(float x) {
    float e = __expf(2.0f * x);
    return 1.0f - __fdividef(2.0f, e + 1.0f);
}

__device__ __forceinline__ void mma_f16(float* d, const uint32_t* a, const uint32_t* b) {
    asm volatile(
        "mma.sync.aligned.m16n8k16.row.col.f32.f16.f16.f32 "
        "{%0,%1,%2,%3}, {%4,%5,%6,%7}, {%8,%9}, {%0,%1,%2,%3};\n"
        : "+f"(d[0]), "+f"(d[1]), "+f"(d[2]), "+f"(d[3])
        : "r"(a[0]), "r"(a[1]), "r"(a[2]), "r"(a[3]), "r"(b[0]), "r"(b[1]));
}

__device__ __forceinline__ void ldsm_x4(uint32_t* r, uint32_t saddr) {
    asm volatile("ldmatrix.sync.aligned.m8n8.x4.shared.b16 {%0,%1,%2,%3}, [%4];"
                 : "=r"(r[0]), "=r"(r[1]), "=r"(r[2]), "=r"(r[3])
                 : "r"(saddr));
}
__device__ __forceinline__ void ldsm_x4_t(uint32_t* r, uint32_t saddr) {
    asm volatile("ldmatrix.sync.aligned.m8n8.x4.trans.shared.b16 {%0,%1,%2,%3}, [%4];"
                 : "=r"(r[0]), "=r"(r[1]), "=r"(r[2]), "=r"(r[3])
                 : "r"(saddr));
}

__device__ __forceinline__ void cp_async16(uint32_t smem_addr, const void* gptr) {
    asm volatile("cp.async.cg.shared.global [%0], [%1], 16;"
                 :: "r"(smem_addr), "l"(gptr));
}
#define CP_COMMIT() asm volatile("cp.async.commit_group;" ::: "memory")
#define CP_WAIT1()  asm volatile("cp.async.wait_group 1;" ::: "memory")

// ---------------------------------------------------------------------------
// Geometry: 128x128 CTA tile, BK=32 (halves), 256 threads (8 warps = 4Mx2N),
// warp tile 32x64, 2x8 m16n8 fragments. 3-stage cp.async pipeline.
// ---------------------------------------------------------------------------
#define BM 128
#define BN 128
#define BK 32
#define LDTH 40                             // MK row stride (halves): 80B -> LDSM conflict-free
#define LDMH 136                            // KM row stride (halves): 272B -> conflict-free
#define STG_MK (BM * LDTH * 2)              // 10240 B / operand / stage
#define GSMEM_MK (6 * STG_MK)               // 61440 B
#define STG_KM (BK * LDMH * 2)              // 8704 B
#define GSMEM_KM (6 * STG_KM)               // 52224 B

// per-thread LDSM source byte offsets within one MK stage
struct LdsmOffs { uint32_t a[2]; uint32_t b[4]; };

__device__ __forceinline__ LdsmOffs make_offs_mk(int warp_row, int warp_col, int lane) {
    LdsmOffs o;
    const int sel = lane >> 3, rin = lane & 7;
#pragma unroll
    for (int i = 0; i < 2; i++) {
        int r = warp_row * 32 + i * 16 + (sel & 1) * 8 + rin;   // m row
        int c = (sel >> 1) * 8;                                 // k halves
        o.a[i] = (uint32_t)((r * LDTH + c) * 2);
    }
#pragma unroll
    for (int jp = 0; jp < 4; jp++) {
        int n = warp_col * 64 + jp * 16 + (sel >> 1) * 8 + rin; // n row
        int c = (sel & 1) * 8;                                  // k halves
        o.b[jp] = (uint32_t)((n * LDTH + c) * 2);
    }
    return o;
}

// one k16 step (MK): 6 LDSM.x4 + 16 MMA
__device__ __forceinline__ void mma_step_mk(float acc[2][8][4],
                                            uint32_t aBase, uint32_t bBase,
                                            const LdsmOffs& o, int ks) {
    const uint32_t kadd = ks * 32;   // 16 halves
    uint32_t afr[2][4];
    ldsm_x4(afr[0], aBase + o.a[0] + kadd);
    ldsm_x4(afr[1], aBase + o.a[1] + kadd);
    uint32_t bfr[4][4];
#pragma unroll
    for (int jp = 0; jp < 4; jp++)
        ldsm_x4(bfr[jp], bBase + o.b[jp] + kadd);
#pragma unroll
    for (int i = 0; i < 2; i++)
#pragma unroll
        for (int j = 0; j < 8; j++)
            mma_f16(acc[i][j], afr[i], &bfr[j >> 1][(j & 1) * 2]);
}

// ============================================================================
// Kernel A: merged f_att GEMM (MK layout). K=2048 as two 1024 halves:
//   half 0: A=srch[b], B=wkTh ; half 1: A=wqh, B=qryh[b]
// Epilogue: fast_tanh -> fp16 g_t1h.
// ============================================================================
__global__ void __launch_bounds__(256, 2)
gemm_fatt()
{
    extern __shared__ uint32_t smem[];
    const uint32_t sBase = (uint32_t)__cvta_generic_to_shared(smem);
    const uint32_t asBase = sBase;
    const uint32_t bsBase = sBase + 3 * STG_MK;

    const int tid = threadIdx.x;
    const int wid = tid >> 5;
    const int lane = tid & 31;
    const int warp_row = wid >> 1;
    const int warp_col = wid & 1;

    const int b  = blockIdx.z;
    const int m0 = blockIdx.y * BM;
    const int n0 = blockIdx.x * BN;

    const __half* a_half[2] = { g_srch + (size_t)b * SS * DD + (size_t)m0 * DD,
                                g_wqh  + (size_t)m0 * DD };
    const __half* b_half[2] = { g_wkTh + (size_t)n0 * DD,
                                g_qryh + (size_t)b * QQ * DD + (size_t)n0 * DD };

    const int l_row = tid >> 2;          // 0..63
    const int l_c8  = (tid & 3) * 8;     // halves 0,8,16,24

    uint32_t wOff[2];
#pragma unroll
    for (int u = 0; u < 2; u++)
        wOff[u] = (uint32_t)(((l_row + 64 * u) * LDTH + l_c8) * 2);

    const LdsmOffs offs = make_offs_mk(warp_row, warp_col, lane);

    float acc[2][8][4];
#pragma unroll
    for (int i = 0; i < 2; i++)
#pragma unroll
        for (int j = 0; j < 8; j++)
#pragma unroll
            for (int r = 0; r < 4; r++) acc[i][j][r] = 0.f;

    const int ntiles = 2048 / BK;   // 64

    // prologue: stages 0,1 (both in half 0)
#pragma unroll
    for (int p = 0; p < 2; p++) {
        const int k0 = p * BK;
        const __half* ap = a_half[0] + (size_t)l_row * DD + k0 + l_c8;
        const __half* bp = b_half[0] + (size_t)l_row * DD + k0 + l_c8;
        const uint32_t so = p * STG_MK;
#pragma unroll
        for (int u = 0; u < 2; u++) {
            cp_async16(asBase + so + wOff[u], ap + (size_t)(64 * u) * DD);
            cp_async16(bsBase + so + wOff[u], bp + (size_t)(64 * u) * DD);
        }
        CP_COMMIT();
    }

    for (int t = 0; t < ntiles; t++) {
        CP_WAIT1();
        __syncthreads();

        if (t + 2 < ntiles) {
            const int tt = t + 2;
            const int h  = tt >> 5;
            const int k0 = (tt & 31) * BK;
            const uint32_t so = (uint32_t)(tt % 3) * STG_MK;
            const __half* ap = a_half[h] + (size_t)l_row * DD + k0 + l_c8;
            const __half* bp = b_half[h] + (size_t)l_row * DD + k0 + l_c8;
#pragma unroll
            for (int u = 0; u < 2; u++) {
                cp_async16(asBase + so + wOff[u], ap + (size_t)(64 * u) * DD);
                cp_async16(bsBase + so + wOff[u], bp + (size_t)(64 * u) * DD);
            }
            CP_COMMIT();
        }

        const uint32_t co = (uint32_t)(t % 3) * STG_MK;
        mma_step_mk(acc, asBase + co, bsBase + co, offs, 0);
        mma_step_mk(acc, asBase + co, bsBase + co, offs, 1);
    }

    __half* Cb = g_t1h + (size_t)b * SS * QQ;
#pragma unroll
    for (int i = 0; i < 2; i++) {
        const int row0 = m0 + warp_row * 32 + i * 16 + (lane >> 2);
#pragma unroll
        for (int j = 0; j < 8; j++) {
            const int col = n0 + warp_col * 64 + j * 8 + 2 * (lane & 3);
#pragma unroll
            for (int r = 0; r < 2; r++) {
                const size_t off = (size_t)(row0 + r * 8) * QQ + col;
                __half2 h = __floats2half2_rn(fast_tanh(acc[i][j][r * 2 + 0]),
                                              fast_tanh(acc[i][j][r * 2 + 1]));
                *reinterpret_cast<__half2*>(Cb + off) = h;
            }
        }
    }
}

// ============================================================================
// Kernel B: sim GEMM (MK). C[b][m][n] = sum_k t1h[b][m][k] * kernTh[n][k], K=2048.
// Epilogue: f32 -> g_t2.
// ============================================================================
__global__ void __launch_bounds__(256, 2)
gemm_sim()
{
    extern __shared__ uint32_t smem[];
    const uint32_t sBase = (uint32_t)__cvta_generic_to_shared(smem);
    const uint32_t asBase = sBase;
    const uint32_t bsBase = sBase + 3 * STG_MK;

    const int tid = threadIdx.x;
    const int wid = tid >> 5;
    const int lane = tid & 31;
    const int warp_row = wid >> 1;
    const int warp_col = wid & 1;

    const int b  = blockIdx.z;
    const int m0 = blockIdx.y * BM;
    const int n0 = blockIdx.x * BN;

    const __half* Ab = g_t1h + (size_t)b * SS * QQ + (size_t)m0 * QQ;
    const __half* Bb = g_kernTh + (size_t)n0 * QQ;

    const int l_row = tid >> 2;
    const int l_c8  = (tid & 3) * 8;

    uint32_t wOff[2];
#pragma unroll
    for (int u = 0; u < 2; u++)
        wOff[u] = (uint32_t)(((l_row + 64 * u) * LDTH + l_c8) * 2);

    const LdsmOffs offs = make_offs_mk(warp_row, warp_col, lane);

    float acc[2][8][4];
#pragma unroll
    for (int i = 0; i < 2; i++)
#pragma unroll
        for (int j = 0; j < 8; j++)
#pragma unroll
            for (int r = 0; r < 4; r++) acc[i][j][r] = 0.f;

    const int ntiles = QQ / BK;   // 64

#pragma unroll
    for (int p = 0; p < 2; p++) {
        const int k0 = p * BK;
        const __half* ap = Ab + (size_t)l_row * QQ + k0 + l_c8;
        const __half* bp = Bb + (size_t)l_row * QQ + k0 + l_c8;
        const uint32_t so = p * STG_MK;
#pragma unroll
        for (int u = 0; u < 2; u++) {
            cp_async16(asBase + so + wOff[u], ap + (size_t)(64 * u) * QQ);
            cp_async16(bsBase + so + wOff[u], bp + (size_t)(64 * u) * QQ);
        }
        CP_COMMIT();
    }

    for (int t = 0; t < ntiles; t++) {
        CP_WAIT1();
        __syncthreads();

        if (t + 2 < ntiles) {
            const int k0 = (t + 2) * BK;
            const uint32_t so = (uint32_t)((t + 2) % 3) * STG_MK;
            const __half* ap = Ab + (size_t)l_row * QQ + k0 + l_c8;
            const __half* bp = Bb + (size_t)l_row * QQ + k0 + l_c8;
#pragma unroll
            for (int u = 0; u < 2; u++) {
                cp_async16(asBase + so + wOff[u], ap + (size_t)(64 * u) * QQ);
                cp_async16(bsBase + so + wOff[u], bp + (size_t)(64 * u) * QQ);
            }
            CP_COMMIT();
        }

        const uint32_t co = (uint32_t)(t % 3) * STG_MK;
        mma_step_mk(acc, asBase + co, bsBase + co, offs, 0);
        mma_step_mk(acc, asBase + co, bsBase + co, offs, 1);
    }

    float* Cb = g_t2 + (size_t)b * SS * QQ;
#pragma unroll
    for (int i = 0; i < 2; i++) {
        const int row0 = m0 + warp_row * 32 + i * 16 + (lane >> 2);
#pragma unroll
        for (int j = 0; j < 8; j++) {
            const int col = n0 + warp_col * 64 + j * 8 + 2 * (lane & 3);
#pragma unroll
            for (int r = 0; r < 2; r++) {
                const size_t off = (size_t)(row0 + r * 8) * QQ + col;
                float2 v;
                v.x = acc[i][j][r * 2 + 0];
                v.y = acc[i][j][r * 2 + 1];
                *reinterpret_cast<float2*>(Cb + off) = v;
            }
        }
    }
}

// ============================================================================
// Kernel C: out[b][q][d] = sum_s ph[b][s][q] * srch[b][s][d]  (KM layout, K=s)
// Uses ldmatrix.trans (b16) for both operands.
// ============================================================================
__global__ void __launch_bounds__(256, 2)
gemm_out(float* __restrict__ C)
{
    extern __shared__ uint32_t smem[];
    const uint32_t sBase = (uint32_t)__cvta_generic_to_shared(smem);
    const uint32_t asBase = sBase;
    const uint32_t bsBase = sBase + 3 * STG_KM;

    const int tid = threadIdx.x;
    const int wid = tid >> 5;
    const int lane = tid & 31;
    const int warp_row = wid >> 1;
    const int warp_col = wid & 1;

    const int b  = blockIdx.z;
    const int m0 = blockIdx.y * BM;   // q
    const int n0 = blockIdx.x * BN;   // d

    const __half* Ab = g_ph + (size_t)b * SS * QQ + m0;
    const __half* Bb = g_srch + (size_t)b * SS * DD + n0;

    const int lk = tid >> 3;          // 0..31 (k rows)
    const int lc = (tid & 7) * 8;     // halves 0..56

    uint32_t w[2];
#pragma unroll
    for (int u = 0; u < 2; u++)
        w[u] = (uint32_t)((lk * LDMH + lc + 64 * u) * 2);

    // trans LDSM offsets
    const int sel = lane >> 3, rin = lane & 7;
    uint32_t oa[2], ob[4];
#pragma unroll
    for (int i = 0; i < 2; i++)
        oa[i] = (uint32_t)((((sel >> 1) * 8 + rin) * LDMH
                           + warp_row * 32 + i * 16 + (sel & 1) * 8) * 2);
#pragma unroll
    for (int jp = 0; jp < 4; jp++)
        ob[jp] = (uint32_t)((((sel & 1) * 8 + rin) * LDMH
                           + warp_col * 64 + jp * 16 + (sel >> 1) * 8) * 2);

    float acc[2][8][4];
#pragma unroll
    for (int i = 0; i < 2; i++)
#pragma unroll
        for (int j = 0; j < 8; j++)
#pragma unroll
            for (int r = 0; r < 4; r++) acc[i][j][r] = 0.f;

    const int ntiles = SS / BK;   // 64

#pragma unroll
    for (int p = 0; p < 2; p++) {
        const __half* ap = Ab + (size_t)(p * BK + lk) * QQ;
        const __half* bp = Bb + (size_t)(p * BK + lk) * DD;
        const uint32_t so = p * STG_KM;
#pragma unroll
        for (int u = 0; u < 2; u++) {
            cp_async16(asBase + so + w[u], ap + lc + 64 * u);
            cp_async16(bsBase + so + w[u], bp + lc + 64 * u);
        }
        CP_COMMIT();
    }

    for (int t = 0; t < ntiles; t++) {
        CP_WAIT1();
        __syncthreads();

        if (t + 2 < ntiles) {
            const int k0 = (t + 2) * BK;
            const uint32_t so = (uint32_t)((t + 2) % 3) * STG_KM;
            const __half* ap = Ab + (size_t)(k0 + lk) * QQ;
            const __half* bp = Bb + (size_t)(k0 + lk) * DD;
#pragma unroll
            for (int u = 0; u < 2; u++) {
                cp_async16(asBase + so + w[u], ap + lc + 64 * u);
                cp_async16(bsBase + so + w[u], bp + lc + 64 * u);
            }
            CP_COMMIT();
        }

        const uint32_t aB = asBase + (uint32_t)(t % 3) * STG_KM;
        const uint32_t bB = bsBase + (uint32_t)(t % 3) * STG_KM;

#pragma unroll
        for (int ks = 0; ks < 2; ks++) {
            const uint32_t kadd = (uint32_t)(ks * 16 * LDMH * 2);
            uint32_t afr[2][4];
            ldsm_x4_t(afr[0], aB + oa[0] + kadd);
            ldsm_x4_t(afr[1], aB + oa[1] + kadd);
            uint32_t bfr[4][4];
#pragma unroll
            for (int jp = 0; jp < 4; jp++)
                ldsm_x4_t(bfr[jp], bB + ob[jp] + kadd);
#pragma unroll
            for (int i = 0; i < 2; i++)
#pragma unroll
                for (int j = 0; j < 8; j++)
                    mma_f16(acc[i][j], afr[i], &bfr[j >> 1][(j & 1) * 2]);
        }
    }

    float* Cb = C + (size_t)b * QQ * DD;
#pragma unroll
    for (int i = 0; i < 2; i++) {
        const int row0 = m0 + warp_row * 32 + i * 16 + (lane >> 2);
#pragma unroll
        for (int j = 0; j < 8; j++) {
            const int col = n0 + warp_col * 64 + j * 8 + 2 * (lane & 3);
#pragma unroll
            for (int r = 0; r < 2; r++) {
                const size_t off = (size_t)(row0 + r * 8) * DD + col;
                float2 v;
                v.x = acc[i][j][r * 2 + 0];
                v.y = acc[i][j][r * 2 + 1];
                *reinterpret_cast<float2*>(Cb + off) = v;
            }
        }
    }
}

// ---------------------------------------------------------------------------
// Merged elementwise f32 -> fp16 over three buffers (one launch)
// ---------------------------------------------------------------------------
#define CVT_N0 ((BB * SS * DD) / 4)   // src
#define CVT_N1 ((BB * QQ * DD) / 4)   // qry
#define CVT_N2 ((SS * DD) / 4)        // wq
#define CVT_TOTAL (CVT_N0 + CVT_N1 + CVT_N2)

__global__ void k_cvt_all(const float4* __restrict__ src, uint2* __restrict__ srch,
                          const float4* __restrict__ qry, uint2* __restrict__ qryh,
                          const float4* __restrict__ wq,  uint2* __restrict__ wqh)
{
    int i = blockIdx.x * blockDim.x + threadIdx.x;
    if (i >= CVT_TOTAL) return;
    const float4* in;
    uint2* out;
    int idx;
    if (i < CVT_N0)                { in = src; out = srch; idx = i; }
    else if (i < CVT_N0 + CVT_N1)  { in = qry; out = qryh; idx = i - CVT_N0; }
    else                           { in = wq;  out = wqh;  idx = i - CVT_N0 - CVT_N1; }
    float4 v = in[idx];
    uint2 o;
    o.x = h2_as_u32(__floats2half2_rn(v.x, v.y));
    o.y = h2_as_u32(__floats2half2_rn(v.z, v.w));
    out[idx] = o;
}

// ---------------------------------------------------------------------------
// Tiled transpose f32 -> fp16: out[c][r] = h(in[r][c])
// ---------------------------------------------------------------------------
__global__ void k_transpose_h(const float* __restrict__ in, __half* __restrict__ out,
                              int R, int C)
{
    __shared__ float tile[32][33];
    const int c0 = blockIdx.x * 32;
    const int r0 = blockIdx.y * 32;

#pragma unroll
    for (int i = threadIdx.y; i < 32; i += 8)
        tile[i][threadIdx.x] = in[(size_t)(r0 + i) * C + c0 + threadIdx.x];
    __syncthreads();
#pragma unroll
    for (int i = threadIdx.y; i < 32; i += 8)
        out[(size_t)(c0 + i) * R + r0 + threadIdx.x] = __float2half_rn(tile[threadIdx.x][i]);
}

// ---------------------------------------------------------------------------
// SMEM-resident row softmax: read f32 g_t2, write fp16 g_ph.
// ---------------------------------------------------------------------------
__global__ void __launch_bounds__(256)
k_softmax()
{
    __shared__ float4 rowv[QQ / 4];   // 8 KB
    __shared__ float red[32];

    const float4* p = reinterpret_cast<const float4*>(g_t2 + (size_t)blockIdx.x * QQ);
    __half2* q = reinterpret_cast<__half2*>(g_ph + (size_t)blockIdx.x * QQ);
    const int tid = threadIdx.x;  // 256

    float m = -INFINITY;
#pragma unroll
    for (int i = tid; i < QQ / 4; i += 256) {
        float4 v = p[i];
        rowv[i] = v;
        m = fmaxf(m, fmaxf(fmaxf(v.x, v.y), fmaxf(v.z, v.w)));
    }
#pragma unroll
    for (int o = 16; o > 0; o >>= 1) m = fmaxf(m, __shfl_xor_sync(0xffffffffu, m, o));
    if ((tid & 31) == 0) red[tid >> 5] = m;
    __syncthreads();
    if (tid < 32) {
        float v = (tid < 8) ? red[tid] : -INFINITY;
#pragma unroll
        for (int o = 4; o > 0; o >>= 1) v = fmaxf(v, __shfl_xor_sync(0xffffffffu, v, o));
        red[tid] = v;
    }
    __syncthreads();
    m = red[0];
    __syncthreads();

    float sum = 0.f;
#pragma unroll
    for (int i = tid; i < QQ / 4; i += 256) {
        float4 v = rowv[i];
        v.x = __expf(v.x - m); v.y = __expf(v.y - m);
        v.z = __expf(v.z - m); v.w = __expf(v.w - m);
        rowv[i] = v;
        sum += v.x + v.y + v.z + v.w;
    }
#pragma unroll
    for (int o = 16; o > 0; o >>= 1) sum += __shfl_xor_sync(0xffffffffu, sum, o);
    if ((tid & 31) == 0) red[tid >> 5] = sum;
    __syncthreads();
    if (tid < 32) {
        float v = (tid < 8) ? red[tid] : 0.f;
#pragma unroll
        for (int o = 4; o > 0; o >>= 1) v += __shfl_xor_sync(0xffffffffu, v, o);
        red[tid] = v;
    }
    __syncthreads();
    const float inv = 1.0f / red[0];

#pragma unroll
    for (int i = tid; i < QQ / 4; i += 256) {
        float4 v = rowv[i];
        q[2 * i + 0] = __floats2half2_rn(v.x * inv, v.y * inv);
        q[2 * i + 1] = __floats2half2_rn(v.z * inv, v.w * inv);
    }
}

// ---------------------------------------------------------------------------
// Launcher
// ---------------------------------------------------------------------------
extern "C" void kernel_launch(void* const* d_in, const int* in_sizes, int n_in,
                              void* d_out, int out_size)
{
    const float* src  = (const float*)d_in[0];  // (B,S,D)
    const float* qry  = (const float*)d_in[1];  // (B,Q,D)
    const float* kern = (const float*)d_in[2];  // (Q,T)
    const float* wk   = (const float*)d_in[3];  // (D,Q)
    const float* wq   = (const float*)d_in[4];  // (S,D)
    float* out = (float*)d_out;                 // (B,Q,D)

    __half *srch, *qryh, *wqh, *wkTh, *kernTh;
    cudaGetSymbolAddress((void**)&srch, g_srch);
    cudaGetSymbolAddress((void**)&qryh, g_qryh);
    cudaGetSymbolAddress((void**)&wqh, g_wqh);
    cudaGetSymbolAddress((void**)&wkTh, g_wkTh);
    cudaGetSymbolAddress((void**)&kernTh, g_kernTh);

    cudaFuncSetAttribute(gemm_fatt, cudaFuncAttributeMaxDynamicSharedMemorySize, GSMEM_MK);
    cudaFuncSetAttribute(gemm_sim,  cudaFuncAttributeMaxDynamicSharedMemorySize, GSMEM_MK);
    cudaFuncSetAttribute(gemm_out,  cudaFuncAttributeMaxDynamicSharedMemorySize, GSMEM_KM);

    // 0) operand prep: one merged fp16 conversion + two fp16 weight transposes
    k_cvt_all<<<(CVT_TOTAL + 255) / 256, 256>>>(
        (const float4*)src, (uint2*)srch,
        (const float4*)qry, (uint2*)qryh,
        (const float4*)wq,  (uint2*)wqh);
    const dim3 tb(32, 8);
    k_transpose_h<<<dim3(QQ / 32, DD / 32), tb>>>(wk, wkTh, DD, QQ);
    k_transpose_h<<<dim3(QQ / 32, QQ / 32), tb>>>(kern, kernTh, QQ, QQ);

    // 1) merged f_att: t1h = tanh(src@wk + wq@qry^T)
    gemm_fatt<<<dim3(QQ / BN, SS / BM, BB), 256, GSMEM_MK>>>();

    // 2) sim: t2 = t1h @ kernTh  (f32 out)  [expected ncu capture slot]
    gemm_sim<<<dim3(QQ / BN, SS / BM, BB), 256, GSMEM_MK>>>();

    // 3) softmax rows -> fp16 probs
    k_softmax<<<BB * SS, 256>>>();

    // 4) out = probs^T @ src
    gemm_out<<<dim3(DD / BN, QQ / BM, BB), 256, GSMEM_KM>>>(out);
}

// round 11
// speedup vs baseline: 14.3987x; 1.0653x over previous
#include <cuda_runtime.h>
#include <cuda_fp16.h>
#include <cstdint>
#include <math.h>

// Shapes (fixed)
#define BB 8
#define SS 2048
#define QQ 2048
#define DD 1024

// ---------------------------------------------------------------------------
// Scratch (device globals). fp16 operands, f32 where accumulation precision matters.
// ---------------------------------------------------------------------------
__device__ __half g_t1h[(size_t)BB * SS * QQ];        // tanh(f_att) fp16
__device__ float  g_t2[(size_t)BB * SS * QQ];         // sim (f32 for softmax)
__device__ __half g_ph[(size_t)BB * SS * QQ];         // softmax probs fp16
__device__ __half g_wkTh[(size_t)QQ * DD];            // wkT[q][d]
__device__ __half g_kernTh[(size_t)QQ * QQ];          // kernT[t][q]
__device__ __half g_srch[(size_t)BB * SS * DD];       // src fp16
__device__ __half g_qryh[(size_t)BB * QQ * DD];       // query fp16
__device__ __half g_wqh[(size_t)SS * DD];             // wq fp16

// ---------------------------------------------------------------------------
// PTX helpers (baseline PTX)
// ---------------------------------------------------------------------------
__device__ __forceinline__ uint32_t h2_as_u32(__half2 h) {
    uint32_t u;
    __builtin_memcpy(&u, &h, sizeof(u));
    return u;
}

__device__ __forceinline__ void mma_f16(float* d, const uint32_t* a, const uint32_t* b) {
    asm volatile(
        "mma.sync.aligned.m16n8k16.row.col.f32.f16.f16.f32 "
        "{%0,%1,%2,%3}, {%4,%5,%6,%7}, {%8,%9}, {%0,%1,%2,%3};\n"
        : "+f"(d[0]), "+f"(d[1]), "+f"(d[2]), "+f"(d[3])
        : "r"(a[0]), "r"(a[1]), "r"(a[2]), "r"(a[3]), "r"(b[0]), "r"(b[1]));
}

__device__ __forceinline__ void ldsm_x4(uint32_t* r, uint32_t saddr) {
    asm volatile("ldmatrix.sync.aligned.m8n8.x4.shared.b16 {%0,%1,%2,%3}, [%4];"
                 : "=r"(r[0]), "=r"(r[1]), "=r"(r[2]), "=r"(r[3])
                 : "r"(saddr));
}
__device__ __forceinline__ void ldsm_x4_t(uint32_t* r, uint32_t saddr) {
    asm volatile("ldmatrix.sync.aligned.m8n8.x4.trans.shared.b16 {%0,%1,%2,%3}, [%4];"
                 : "=r"(r[0]), "=r"(r[1]), "=r"(r[2]), "=r"(r[3])
                 : "r"(saddr));
}

__device__ __forceinline__ void cp_async16(uint32_t smem_addr, const void* gptr) {
    asm volatile("cp.async.cg.shared.global [%0], [%1], 16;"
                 :: "r"(smem_addr), "l"(gptr));
}
#define CP_COMMIT() asm volatile("cp.async.commit_group;" ::: "memory")
#define CP_WAIT0()  asm volatile("cp.async.wait_group 0;" ::: "memory")

// ---------------------------------------------------------------------------
// Geometry: 128x128 CTA tile, BK=64 (halves), 256 threads (8 warps = 4Mx2N),
// warp tile 32x64. 2-stage cp.async pipeline, 4 k16-steps per tile.
// ---------------------------------------------------------------------------
#define BM 128
#define BN 128
#define BK 64
#define LDTH 72                             // MK row stride (halves): 144B -> LDSM conflict-free
#define LDMH 136                            // KM row stride (halves): 272B -> conflict-free
#define STG_MK (BM * LDTH * 2)              // 18432 B / operand / stage
#define GSMEM_MK (4 * STG_MK)               // 73728 B: A[2] + B[2]
#define STG_KM (BK * LDMH * 2)              // 17408 B
#define GSMEM_KM (4 * STG_KM)               // 69632 B

// per-thread LDSM source byte offsets within one MK stage
struct LdsmOffs { uint32_t a[2]; uint32_t b[4]; };

__device__ __forceinline__ LdsmOffs make_offs_mk(int warp_row, int warp_col, int lane) {
    LdsmOffs o;
    const int sel = lane >> 3, rin = lane & 7;
#pragma unroll
    for (int i = 0; i < 2; i++) {
        int r = warp_row * 32 + i * 16 + (sel & 1) * 8 + rin;   // m row
        int c = (sel >> 1) * 8;                                 // k halves
        o.a[i] = (uint32_t)((r * LDTH + c) * 2);
    }
#pragma unroll
    for (int jp = 0; jp < 4; jp++) {
        int n = warp_col * 64 + jp * 16 + (sel >> 1) * 8 + rin; // n row
        int c = (sel & 1) * 8;                                  // k halves
        o.b[jp] = (uint32_t)((n * LDTH + c) * 2);
    }
    return o;
}

// one k16 step (MK): 6 LDSM.x4 + 16 MMA
__device__ __forceinline__ void mma_step_mk(float acc[2][8][4],
                                            uint32_t aBase, uint32_t bBase,
                                            const LdsmOffs& o, int ks) {
    const uint32_t kadd = ks * 32;   // 16 halves = 32 B
    uint32_t afr[2][4];
    ldsm_x4(afr[0], aBase + o.a[0] + kadd);
    ldsm_x4(afr[1], aBase + o.a[1] + kadd);
    uint32_t bfr[4][4];
#pragma unroll
    for (int jp = 0; jp < 4; jp++)
        ldsm_x4(bfr[jp], bBase + o.b[jp] + kadd);
#pragma unroll
    for (int i = 0; i < 2; i++)
#pragma unroll
        for (int j = 0; j < 8; j++)
            mma_f16(acc[i][j], afr[i], &bfr[j >> 1][(j & 1) * 2]);
}

// ============================================================================
// Kernel A: merged f_att GEMM (MK layout). K=2048 as two 1024 halves:
//   tiles 0..15: A=srch[b], B=wkTh ; tiles 16..31: A=wqh, B=qryh[b]
// Epilogue: tanhf -> fp16 g_t1h.
// ============================================================================
__global__ void __launch_bounds__(256, 2)
gemm_fatt()
{
    extern __shared__ uint32_t smem[];
    const uint32_t sBase = (uint32_t)__cvta_generic_to_shared(smem);
    const uint32_t asBase = sBase;
    const uint32_t bsBase = sBase + 2 * STG_MK;

    const int tid = threadIdx.x;
    const int wid = tid >> 5;
    const int lane = tid & 31;
    const int warp_row = wid >> 1;
    const int warp_col = wid & 1;

    const int b  = blockIdx.z;
    const int m0 = blockIdx.y * BM;
    const int n0 = blockIdx.x * BN;

    const __half* a_half[2] = { g_srch + (size_t)b * SS * DD + (size_t)m0 * DD,
                                g_wqh  + (size_t)m0 * DD };
    const __half* b_half[2] = { g_wkTh + (size_t)n0 * DD,
                                g_qryh + (size_t)b * QQ * DD + (size_t)n0 * DD };

    const int l_row = tid >> 3;          // 0..31
    const int l_c8  = (tid & 7) * 8;     // halves 0..56

    uint32_t wOff[4];
#pragma unroll
    for (int u = 0; u < 4; u++)
        wOff[u] = (uint32_t)(((l_row + 32 * u) * LDTH + l_c8) * 2);

    const LdsmOffs offs = make_offs_mk(warp_row, warp_col, lane);

    float acc[2][8][4];
#pragma unroll
    for (int i = 0; i < 2; i++)
#pragma unroll
        for (int j = 0; j < 8; j++)
#pragma unroll
            for (int r = 0; r < 4; r++) acc[i][j][r] = 0.f;

    const int ntiles = 2048 / BK;   // 32

    // prologue: tile 0 (half 0)
    {
        const __half* ap = a_half[0] + (size_t)l_row * DD + l_c8;
        const __half* bp = b_half[0] + (size_t)l_row * DD + l_c8;
#pragma unroll
        for (int u = 0; u < 4; u++) {
            cp_async16(asBase + wOff[u], ap + (size_t)(32 * u) * DD);
            cp_async16(bsBase + wOff[u], bp + (size_t)(32 * u) * DD);
        }
        CP_COMMIT();
    }

    for (int t = 0; t < ntiles; t++) {
        CP_WAIT0();
        __syncthreads();

        if (t + 1 < ntiles) {
            const int tt = t + 1;
            const int h  = tt >> 4;
            const int k0 = (tt & 15) * BK;
            const uint32_t so = (uint32_t)(tt & 1) * STG_MK;
            const __half* ap = a_half[h] + (size_t)l_row * DD + k0 + l_c8;
            const __half* bp = b_half[h] + (size_t)l_row * DD + k0 + l_c8;
#pragma unroll
            for (int u = 0; u < 4; u++) {
                cp_async16(asBase + so + wOff[u], ap + (size_t)(32 * u) * DD);
                cp_async16(bsBase + so + wOff[u], bp + (size_t)(32 * u) * DD);
            }
            CP_COMMIT();
        }

        const uint32_t co = (uint32_t)(t & 1) * STG_MK;
#pragma unroll
        for (int ks = 0; ks < 4; ks++)
            mma_step_mk(acc, asBase + co, bsBase + co, offs, ks);
    }

    __half* Cb = g_t1h + (size_t)b * SS * QQ;
#pragma unroll
    for (int i = 0; i < 2; i++) {
        const int row0 = m0 + warp_row * 32 + i * 16 + (lane >> 2);
#pragma unroll
        for (int j = 0; j < 8; j++) {
            const int col = n0 + warp_col * 64 + j * 8 + 2 * (lane & 3);
#pragma unroll
            for (int r = 0; r < 2; r++) {
                const size_t off = (size_t)(row0 + r * 8) * QQ + col;
                __half2 h = __floats2half2_rn(tanhf(acc[i][j][r * 2 + 0]),
                                              tanhf(acc[i][j][r * 2 + 1]));
                *reinterpret_cast<__half2*>(Cb + off) = h;
            }
        }
    }
}

// ============================================================================
// Kernel B: sim GEMM (MK). C[b][m][n] = sum_k t1h[b][m][k] * kernTh[n][k], K=2048.
// ============================================================================
__global__ void __launch_bounds__(256, 2)
gemm_sim()
{
    extern __shared__ uint32_t smem[];
    const uint32_t sBase = (uint32_t)__cvta_generic_to_shared(smem);
    const uint32_t asBase = sBase;
    const uint32_t bsBase = sBase + 2 * STG_MK;

    const int tid = threadIdx.x;
    const int wid = tid >> 5;
    const int lane = tid & 31;
    const int warp_row = wid >> 1;
    const int warp_col = wid & 1;

    const int b  = blockIdx.z;
    const int m0 = blockIdx.y * BM;
    const int n0 = blockIdx.x * BN;

    const __half* Ab = g_t1h + (size_t)b * SS * QQ + (size_t)m0 * QQ;
    const __half* Bb = g_kernTh + (size_t)n0 * QQ;

    const int l_row = tid >> 3;
    const int l_c8  = (tid & 7) * 8;

    uint32_t wOff[4];
#pragma unroll
    for (int u = 0; u < 4; u++)
        wOff[u] = (uint32_t)(((l_row + 32 * u) * LDTH + l_c8) * 2);

    const LdsmOffs offs = make_offs_mk(warp_row, warp_col, lane);

    float acc[2][8][4];
#pragma unroll
    for (int i = 0; i < 2; i++)
#pragma unroll
        for (int j = 0; j < 8; j++)
#pragma unroll
            for (int r = 0; r < 4; r++) acc[i][j][r] = 0.f;

    const int ntiles = QQ / BK;   // 32

    {
        const __half* ap = Ab + (size_t)l_row * QQ + l_c8;
        const __half* bp = Bb + (size_t)l_row * QQ + l_c8;
#pragma unroll
        for (int u = 0; u < 4; u++) {
            cp_async16(asBase + wOff[u], ap + (size_t)(32 * u) * QQ);
            cp_async16(bsBase + wOff[u], bp + (size_t)(32 * u) * QQ);
        }
        CP_COMMIT();
    }

    for (int t = 0; t < ntiles; t++) {
        CP_WAIT0();
        __syncthreads();

        if (t + 1 < ntiles) {
            const int k0 = (t + 1) * BK;
            const uint32_t so = (uint32_t)((t + 1) & 1) * STG_MK;
            const __half* ap = Ab + (size_t)l_row * QQ + k0 + l_c8;
            const __half* bp = Bb + (size_t)l_row * QQ + k0 + l_c8;
#pragma unroll
            for (int u = 0; u < 4; u++) {
                cp_async16(asBase + so + wOff[u], ap + (size_t)(32 * u) * QQ);
                cp_async16(bsBase + so + wOff[u], bp + (size_t)(32 * u) * QQ);
            }
            CP_COMMIT();
        }

        const uint32_t co = (uint32_t)(t & 1) * STG_MK;
#pragma unroll
        for (int ks = 0; ks < 4; ks++)
            mma_step_mk(acc, asBase + co, bsBase + co, offs, ks);
    }

    float* Cb = g_t2 + (size_t)b * SS * QQ;
#pragma unroll
    for (int i = 0; i < 2; i++) {
        const int row0 = m0 + warp_row * 32 + i * 16 + (lane >> 2);
#pragma unroll
        for (int j = 0; j < 8; j++) {
            const int col = n0 + warp_col * 64 + j * 8 + 2 * (lane & 3);
#pragma unroll
            for (int r = 0; r < 2; r++) {
                const size_t off = (size_t)(row0 + r * 8) * QQ + col;
                float2 v;
                v.x = acc[i][j][r * 2 + 0];
                v.y = acc[i][j][r * 2 + 1];
                *reinterpret_cast<float2*>(Cb + off) = v;
            }
        }
    }
}

// ============================================================================
// Kernel C: out[b][q][d] = sum_s ph[b][s][q] * srch[b][s][d]  (KM layout, K=s)
// ldmatrix.trans for both operands. BK=64, 2-stage.
// ============================================================================
__global__ void __launch_bounds__(256, 2)
gemm_out(float* __restrict__ C)
{
    extern __shared__ uint32_t smem[];
    const uint32_t sBase = (uint32_t)__cvta_generic_to_shared(smem);
    const uint32_t asBase = sBase;
    const uint32_t bsBase = sBase + 2 * STG_KM;

    const int tid = threadIdx.x;
    const int wid = tid >> 5;
    const int lane = tid & 31;
    const int warp_row = wid >> 1;
    const int warp_col = wid & 1;

    const int b  = blockIdx.z;
    const int m0 = blockIdx.y * BM;   // q
    const int n0 = blockIdx.x * BN;   // d

    const __half* Ab = g_ph + (size_t)b * SS * QQ + m0;
    const __half* Bb = g_srch + (size_t)b * SS * DD + n0;

    const int lk = tid >> 3;          // 0..31
    const int lc = (tid & 7) * 8;     // halves 0..56

    // 4 chunks: rows {lk, lk+32} x cols {lc, lc+64}
    uint32_t w[4];
    int wr[4], wc[4];
#pragma unroll
    for (int u = 0; u < 4; u++) {
        wr[u] = lk + 32 * (u >> 1);
        wc[u] = lc + 64 * (u & 1);
        w[u] = (uint32_t)((wr[u] * LDMH + wc[u]) * 2);
    }

    // trans LDSM offsets
    const int sel = lane >> 3, rin = lane & 7;
    uint32_t oa[2], ob[4];
#pragma unroll
    for (int i = 0; i < 2; i++)
        oa[i] = (uint32_t)((((sel >> 1) * 8 + rin) * LDMH
                           + warp_row * 32 + i * 16 + (sel & 1) * 8) * 2);
#pragma unroll
    for (int jp = 0; jp < 4; jp++)
        ob[jp] = (uint32_t)((((sel & 1) * 8 + rin) * LDMH
                           + warp_col * 64 + jp * 16 + (sel >> 1) * 8) * 2);

    float acc[2][8][4];
#pragma unroll
    for (int i = 0; i < 2; i++)
#pragma unroll
        for (int j = 0; j < 8; j++)
#pragma unroll
            for (int r = 0; r < 4; r++) acc[i][j][r] = 0.f;

    const int ntiles = SS / BK;   // 32

    {
#pragma unroll
        for (int u = 0; u < 4; u++) {
            cp_async16(asBase + w[u], Ab + (size_t)wr[u] * QQ + wc[u]);
            cp_async16(bsBase + w[u], Bb + (size_t)wr[u] * DD + wc[u]);
        }
        CP_COMMIT();
    }

    for (int t = 0; t < ntiles; t++) {
        CP_WAIT0();
        __syncthreads();

        if (t + 1 < ntiles) {
            const int k0 = (t + 1) * BK;
            const uint32_t so = (uint32_t)((t + 1) & 1) * STG_KM;
#pragma unroll
            for (int u = 0; u < 4; u++) {
                cp_async16(asBase + so + w[u], Ab + (size_t)(k0 + wr[u]) * QQ + wc[u]);
                cp_async16(bsBase + so + w[u], Bb + (size_t)(k0 + wr[u]) * DD + wc[u]);
            }
            CP_COMMIT();
        }

        const uint32_t aB = asBase + (uint32_t)(t & 1) * STG_KM;
        const uint32_t bB = bsBase + (uint32_t)(t & 1) * STG_KM;

#pragma unroll
        for (int ks = 0; ks < 4; ks++) {
            const uint32_t kadd = (uint32_t)(ks * 16 * LDMH * 2);
            uint32_t afr[2][4];
            ldsm_x4_t(afr[0], aB + oa[0] + kadd);
            ldsm_x4_t(afr[1], aB + oa[1] + kadd);
            uint32_t bfr[4][4];
#pragma unroll
            for (int jp = 0; jp < 4; jp++)
                ldsm_x4_t(bfr[jp], bB + ob[jp] + kadd);
#pragma unroll
            for (int i = 0; i < 2; i++)
#pragma unroll
                for (int j = 0; j < 8; j++)
                    mma_f16(acc[i][j], afr[i], &bfr[j >> 1][(j & 1) * 2]);
        }
    }

    float* Cb = C + (size_t)b * QQ * DD;
#pragma unroll
    for (int i = 0; i < 2; i++) {
        const int row0 = m0 + warp_row * 32 + i * 16 + (lane >> 2);
#pragma unroll
        for (int j = 0; j < 8; j++) {
            const int col = n0 + warp_col * 64 + j * 8 + 2 * (lane & 3);
#pragma unroll
            for (int r = 0; r < 2; r++) {
                const size_t off = (size_t)(row0 + r * 8) * DD + col;
                float2 v;
                v.x = acc[i][j][r * 2 + 0];
                v.y = acc[i][j][r * 2 + 1];
                *reinterpret_cast<float2*>(Cb + off) = v;
            }
        }
    }
}

// ---------------------------------------------------------------------------
// Merged elementwise f32 -> fp16 over three buffers (one launch)
// ---------------------------------------------------------------------------
#define CVT_N0 ((BB * SS * DD) / 4)   // src
#define CVT_N1 ((BB * QQ * DD) / 4)   // qry
#define CVT_N2 ((SS * DD) / 4)        // wq
#define CVT_TOTAL (CVT_N0 + CVT_N1 + CVT_N2)

__global__ void k_cvt_all(const float4* __restrict__ src, uint2* __restrict__ srch,
                          const float4* __restrict__ qry, uint2* __restrict__ qryh,
                          const float4* __restrict__ wq,  uint2* __restrict__ wqh)
{
    int i = blockIdx.x * blockDim.x + threadIdx.x;
    if (i >= CVT_TOTAL) return;
    const float4* in;
    uint2* out;
    int idx;
    if (i < CVT_N0)                { in = src; out = srch; idx = i; }
    else if (i < CVT_N0 + CVT_N1)  { in = qry; out = qryh; idx = i - CVT_N0; }
    else                           { in = wq;  out = wqh;  idx = i - CVT_N0 - CVT_N1; }
    float4 v = in[idx];
    uint2 o;
    o.x = h2_as_u32(__floats2half2_rn(v.x, v.y));
    o.y = h2_as_u32(__floats2half2_rn(v.z, v.w));
    out[idx] = o;
}

// ---------------------------------------------------------------------------
// Tiled transpose f32 -> fp16: out[c][r] = h(in[r][c])
// ---------------------------------------------------------------------------
__global__ void k_transpose_h(const float* __restrict__ in, __half* __restrict__ out,
                              int R, int C)
{
    __shared__ float tile[32][33];
    const int c0 = blockIdx.x * 32;
    const int r0 = blockIdx.y * 32;

#pragma unroll
    for (int i = threadIdx.y; i < 32; i += 8)
        tile[i][threadIdx.x] = in[(size_t)(r0 + i) * C + c0 + threadIdx.x];
    __syncthreads();
#pragma unroll
    for (int i = threadIdx.y; i < 32; i += 8)
        out[(size_t)(c0 + i) * R + r0 + threadIdx.x] = __float2half_rn(tile[threadIdx.x][i]);
}

// ---------------------------------------------------------------------------
// SMEM-resident row softmax: read f32 g_t2, write fp16 g_ph.
// ---------------------------------------------------------------------------
__global__ void __launch_bounds__(256)
k_softmax()
{
    __shared__ float4 rowv[QQ / 4];   // 8 KB
    __shared__ float red[32];

    const float4* p = reinterpret_cast<const float4*>(g_t2 + (size_t)blockIdx.x * QQ);
    __half2* q = reinterpret_cast<__half2*>(g_ph + (size_t)blockIdx.x * QQ);
    const int tid = threadIdx.x;  // 256

    float m = -INFINITY;
#pragma unroll
    for (int i = tid; i < QQ / 4; i += 256) {
        float4 v = p[i];
        rowv[i] = v;
        m = fmaxf(m, fmaxf(fmaxf(v.x, v.y), fmaxf(v.z, v.w)));
    }
#pragma unroll
    for (int o = 16; o > 0; o >>= 1) m = fmaxf(m, __shfl_xor_sync(0xffffffffu, m, o));
    if ((tid & 31) == 0) red[tid >> 5] = m;
    __syncthreads();
    if (tid < 32) {
        float v = (tid < 8) ? red[tid] : -INFINITY;
#pragma unroll
        for (int o = 4; o > 0; o >>= 1) v = fmaxf(v, __shfl_xor_sync(0xffffffffu, v, o));
        red[tid] = v;
    }
    __syncthreads();
    m = red[0];
    __syncthreads();

    float sum = 0.f;
#pragma unroll
    for (int i = tid; i < QQ / 4; i += 256) {
        float4 v = rowv[i];
        v.x = __expf(v.x - m); v.y = __expf(v.y - m);
        v.z = __expf(v.z - m); v.w = __expf(v.w - m);
        rowv[i] = v;
        sum += v.x + v.y + v.z + v.w;
    }
#pragma unroll
    for (int o = 16; o > 0; o >>= 1) sum += __shfl_xor_sync(0xffffffffu, sum, o);
    if ((tid & 31) == 0) red[tid >> 5] = sum;
    __syncthreads();
    if (tid < 32) {
        float v = (tid < 8) ? red[tid] : 0.f;
#pragma unroll
        for (int o = 4; o > 0; o >>= 1) v += __shfl_xor_sync(0xffffffffu, v, o);
        red[tid] = v;
    }
    __syncthreads();
    const float inv = 1.0f / red[0];

#pragma unroll
    for (int i = tid; i < QQ / 4; i += 256) {
        float4 v = rowv[i];
        q[2 * i + 0] = __floats2half2_rn(v.x * inv, v.y * inv);
        q[2 * i + 1] = __floats2half2_rn(v.z * inv, v.w * inv);
    }
}

// ---------------------------------------------------------------------------
// Launcher
// ---------------------------------------------------------------------------
extern "C" void kernel_launch(void* const* d_in, const int* in_sizes, int n_in,
                              void* d_out, int out_size)
{
    const float* src  = (const float*)d_in[0];  // (B,S,D)
    const float* qry  = (const float*)d_in[1];  // (B,Q,D)
    const float* kern = (const float*)d_in[2];  // (Q,T)
    const float* wk   = (const float*)d_in[3];  // (D,Q)
    const float* wq   = (const float*)d_in[4];  // (S,D)
    float* out = (float*)d_out;                 // (B,Q,D)

    __half *srch, *qryh, *wqh, *wkTh, *kernTh;
    cudaGetSymbolAddress((void**)&srch, g_srch);
    cudaGetSymbolAddress((void**)&qryh, g_qryh);
    cudaGetSymbolAddress((void**)&wqh, g_wqh);
    cudaGetSymbolAddress((void**)&wkTh, g_wkTh);
    cudaGetSymbolAddress((void**)&kernTh, g_kernTh);

    cudaFuncSetAttribute(gemm_fatt, cudaFuncAttributeMaxDynamicSharedMemorySize, GSMEM_MK);
    cudaFuncSetAttribute(gemm_sim,  cudaFuncAttributeMaxDynamicSharedMemorySize, GSMEM_MK);
    cudaFuncSetAttribute(gemm_out,  cudaFuncAttributeMaxDynamicSharedMemorySize, GSMEM_KM);

    // 0) operand prep: merged fp16 conversion + two fp16 weight transposes
    k_cvt_all<<<(CVT_TOTAL + 255) / 256, 256>>>(
        (const float4*)src, (uint2*)srch,
        (const float4*)qry, (uint2*)qryh,
        (const float4*)wq,  (uint2*)wqh);
    const dim3 tb(32, 8);
    k_transpose_h<<<dim3(QQ / 32, DD / 32), tb>>>(wk, wkTh, DD, QQ);
    k_transpose_h<<<dim3(QQ / 32, QQ / 32), tb>>>(kern, kernTh, QQ, QQ);

    // 1) merged f_att: t1h = tanh(src@wk + wq@qry^T)
    gemm_fatt<<<dim3(QQ / BN, SS / BM, BB), 256, GSMEM_MK>>>();

    // 2) sim: t2 = t1h @ kernTh  (f32 out)
    gemm_sim<<<dim3(QQ / BN, SS / BM, BB), 256, GSMEM_MK>>>();

    // 3) softmax rows -> fp16 probs
    k_softmax<<<BB * SS, 256>>>();

    // 4) out = probs^T @ src
    gemm_out<<<dim3(DD / BN, QQ / BM, BB), 256, GSMEM_KM>>>(out);
}